// round 1
// baseline (speedup 1.0000x reference)
#include <cuda_runtime.h>
#include <math.h>

#define T_TOK 65536      // B * (H/2) * (W/2)
#define K_REAL 1156      // (256 + 32 + 1) * 4
#define KP 1168          // padded to multiple of 16
#define HID 1024
#define NOUT 256

// scratch (device globals: allocation-free per harness rules)
__device__ __align__(16) float g_P[(size_t)T_TOK * KP];    // 306 MB
__device__ __align__(16) float g_W1p[HID * KP];            // 4.8 MB
__device__ __align__(16) float g_H[(size_t)T_TOK * HID];   // 268 MB

// ---------------------------------------------------------------------------
// Kernel 1: zero-pad W1 (1024 x 1156) -> g_W1p (1024 x 1168)
// ---------------------------------------------------------------------------
__global__ void pad_w1_kernel(const float* __restrict__ w1) {
    int idx = blockIdx.x * blockDim.x + threadIdx.x;
    if (idx >= HID * KP) return;
    int n = idx / KP;
    int k = idx - n * KP;
    g_W1p[idx] = (k < K_REAL) ? w1[n * K_REAL + k] : 0.0f;
}

// ---------------------------------------------------------------------------
// Kernel 2: build patchified input P (65536 x 1168).
// Row t = b*4096 + i*64 + j. Col k = c*4 + sy*2 + sx (space-to-depth).
// Channels: [0,256) gestalt*mask, [256,288) interleaved cos embedding * mask,
// 288 depth*mask, [289,292) zero pad.
// Embedding argument computed with strict IEEE fp32 ops to bit-match the
// reference (large args: 1 ulp in the argument matters), cos via double.
// ---------------------------------------------------------------------------
__global__ void build_p_kernel(const float* __restrict__ pos,
                               const float* __restrict__ gestalt,
                               const float* __restrict__ mask,
                               const float* __restrict__ depth) {
    const int CSL = KP / 4;  // 292 channel slots
    int idx = blockIdx.x * blockDim.x + threadIdx.x;
    if (idx >= T_TOK * CSL) return;
    int t = idx / CSL;
    int c = idx - t * CSL;

    int b   = t >> 12;
    int rem = t & 4095;
    int i   = rem >> 6;
    int j   = rem & 63;

    float4 v;
    if (c >= 289) {
        v = make_float4(0.f, 0.f, 0.f, 0.f);
    } else {
        int pbase = b * 16384 + (i * 2) * 128 + (j * 2);
        float m00 = mask[pbase];
        float m01 = mask[pbase + 1];
        float m10 = mask[pbase + 128];
        float m11 = mask[pbase + 129];

        if (c < 256) {
            float g = gestalt[b * 256 + c];
            v = make_float4(g * m00, g * m01, g * m10, g * m11);
        } else if (c < 288) {
            int e = c - 256;
            int f = e >> 1;
            float fs = (float)(1 << f);  // 2^f, exact
            const float HALF_PI = 1.57079632679489661923f;
            float pw   = pos[b * 4 + 3];
            float stdv = __fdiv_rn(0.1f, fminf(fmaxf(pw, 0.0078125f), 0.5f));
            if ((e & 1) == 0) {
                // cos_x: depends on w = 2j + sx
                float x  = fminf(fmaxf(pos[b * 4 + 0], -1.f), 1.f);
                float g0 = __fsub_rn(__fmul_rn(__fdiv_rn((float)(2 * j),     127.0f), 2.0f), 1.0f);
                float g1 = __fsub_rn(__fmul_rn(__fdiv_rn((float)(2 * j + 1), 127.0f), 2.0f), 1.0f);
                float a0 = __fmul_rn(__fmul_rn(__fmul_rn(__fsub_rn(g0, x), stdv), HALF_PI), fs);
                float a1 = __fmul_rn(__fmul_rn(__fmul_rn(__fsub_rn(g1, x), stdv), HALF_PI), fs);
                float c0 = (float)cos((double)a0);
                float c1 = (float)cos((double)a1);
                v = make_float4(c0 * m00, c1 * m01, c0 * m10, c1 * m11);
            } else {
                // cos_y: depends on h = 2i + sy
                float y  = fminf(fmaxf(pos[b * 4 + 1], -1.f), 1.f);
                float g0 = __fsub_rn(__fmul_rn(__fdiv_rn((float)(2 * i),     127.0f), 2.0f), 1.0f);
                float g1 = __fsub_rn(__fmul_rn(__fdiv_rn((float)(2 * i + 1), 127.0f), 2.0f), 1.0f);
                float a0 = __fmul_rn(__fmul_rn(__fmul_rn(__fsub_rn(g0, y), stdv), HALF_PI), fs);
                float a1 = __fmul_rn(__fmul_rn(__fmul_rn(__fsub_rn(g1, y), stdv), HALF_PI), fs);
                float c0 = (float)cos((double)a0);
                float c1 = (float)cos((double)a1);
                v = make_float4(c0 * m00, c0 * m01, c1 * m10, c1 * m11);
            }
        } else {  // c == 288: depth * mask
            v = make_float4(depth[pbase]       * m00,
                            depth[pbase + 1]   * m01,
                            depth[pbase + 128] * m10,
                            depth[pbase + 129] * m11);
        }
    }
    *(float4*)(g_P + (size_t)t * KP + c * 4) = v;
}

// ---------------------------------------------------------------------------
// fp32 SGEMM: C[M,N] = A[M,K] * B[N,K]^T (+bias, epilogue)
// BM=BN=128, BK=16, 256 threads, 8x8 per thread.
// EPI 0: SiLU -> g_H (row-major, ld=1024)
// EPI 1: +bias -> output tensor (B,256,64,64) scatter
// ---------------------------------------------------------------------------
__device__ __forceinline__ float silu_f(float x) {
    return x / (1.0f + expf(-x));
}

template <int EPI>
__device__ __forceinline__ void sgemm_body(const float* __restrict__ A,
                                           const float* __restrict__ Bm,
                                           const float* __restrict__ bias,
                                           float* __restrict__ C,
                                           int K, int lda, int ldb) {
    __shared__ __align__(16) float As[16][128];
    __shared__ __align__(16) float Bs[16][128];

    const int tid = threadIdx.x;
    const int m0 = blockIdx.y * 128;
    const int n0 = blockIdx.x * 128;

    const int lr = tid >> 2;          // 0..63 (row within tile)
    const int lc = (tid & 3) << 2;    // 0,4,8,12 (col group)

    const int tx = tid & 15;          // n-thread
    const int ty = tid >> 4;          // m-thread

    float acc[8][8];
#pragma unroll
    for (int i = 0; i < 8; i++)
#pragma unroll
        for (int j = 0; j < 8; j++) acc[i][j] = 0.0f;

    const float* Aptr = A + (size_t)m0 * lda;
    const float* Bptr = Bm + (size_t)n0 * ldb;

    for (int k0 = 0; k0 < K; k0 += 16) {
#pragma unroll
        for (int half = 0; half < 2; half++) {
            int row = lr + half * 64;
            float4 va = *(const float4*)(Aptr + (size_t)row * lda + k0 + lc);
            As[lc + 0][row] = va.x;
            As[lc + 1][row] = va.y;
            As[lc + 2][row] = va.z;
            As[lc + 3][row] = va.w;
            float4 vb = *(const float4*)(Bptr + (size_t)row * ldb + k0 + lc);
            Bs[lc + 0][row] = vb.x;
            Bs[lc + 1][row] = vb.y;
            Bs[lc + 2][row] = vb.z;
            Bs[lc + 3][row] = vb.w;
        }
        __syncthreads();
#pragma unroll
        for (int k = 0; k < 16; k++) {
            float a[8], bb[8];
            *(float4*)&a[0]  = *(const float4*)&As[k][ty * 4];
            *(float4*)&a[4]  = *(const float4*)&As[k][ty * 4 + 64];
            *(float4*)&bb[0] = *(const float4*)&Bs[k][tx * 4];
            *(float4*)&bb[4] = *(const float4*)&Bs[k][tx * 4 + 64];
#pragma unroll
            for (int i = 0; i < 8; i++)
#pragma unroll
                for (int j = 0; j < 8; j++) acc[i][j] += a[i] * bb[j];
        }
        __syncthreads();
    }

    // bias values for this thread's 8 columns
    float bv[8];
#pragma unroll
    for (int j = 0; j < 8; j++) {
        int n = n0 + tx * 4 + (j & 3) + ((j >> 2) << 6);
        bv[j] = bias[n];
    }

    if (EPI == 0) {
#pragma unroll
        for (int i = 0; i < 8; i++) {
            int m = m0 + ty * 4 + (i & 3) + ((i >> 2) << 6);
            float4 o0, o1;
            o0.x = silu_f(acc[i][0] + bv[0]);
            o0.y = silu_f(acc[i][1] + bv[1]);
            o0.z = silu_f(acc[i][2] + bv[2]);
            o0.w = silu_f(acc[i][3] + bv[3]);
            o1.x = silu_f(acc[i][4] + bv[4]);
            o1.y = silu_f(acc[i][5] + bv[5]);
            o1.z = silu_f(acc[i][6] + bv[6]);
            o1.w = silu_f(acc[i][7] + bv[7]);
            float* crow = C + (size_t)m * HID + n0 + tx * 4;
            *(float4*)(crow) = o0;
            *(float4*)(crow + 64) = o1;
        }
    } else {
        // output layout: out[b, n, i, j] = C[((m>>12)<<20) + (n<<12) + (m&4095)]
#pragma unroll
        for (int i = 0; i < 8; i++) {
            int m = m0 + ty * 4 + (i & 3) + ((i >> 2) << 6);
            size_t obase = ((size_t)(m >> 12) << 20) + (size_t)(m & 4095);
#pragma unroll
            for (int j = 0; j < 8; j++) {
                int n = n0 + tx * 4 + (j & 3) + ((j >> 2) << 6);
                C[obase + ((size_t)n << 12)] = acc[i][j] + bv[j];
            }
        }
    }
}

__global__ __launch_bounds__(256, 2) void gemm1_kernel(const float* __restrict__ bias1) {
    sgemm_body<0>(g_P, g_W1p, bias1, g_H, KP, KP, KP);
}

__global__ __launch_bounds__(256, 2) void gemm2_kernel(const float* __restrict__ w2,
                                                       const float* __restrict__ bias2,
                                                       float* __restrict__ out) {
    sgemm_body<1>(g_H, w2, bias2, out, HID, HID, HID);
}

// ---------------------------------------------------------------------------
extern "C" void kernel_launch(void* const* d_in, const int* in_sizes, int n_in,
                              void* d_out, int out_size) {
    const float* position = (const float*)d_in[0];
    const float* gestalt  = (const float*)d_in[1];
    const float* mask     = (const float*)d_in[2];
    const float* depth    = (const float*)d_in[3];
    const float* w1       = (const float*)d_in[4];
    const float* b1       = (const float*)d_in[5];
    const float* w2       = (const float*)d_in[6];
    const float* b2       = (const float*)d_in[7];
    float* out = (float*)d_out;

    (void)in_sizes; (void)n_in; (void)out_size;

    pad_w1_kernel<<<(HID * KP + 255) / 256, 256>>>(w1);

    const int csl = KP / 4;
    build_p_kernel<<<(T_TOK * csl + 255) / 256, 256>>>(position, gestalt, mask, depth);

    dim3 grid1(HID / 128, T_TOK / 128);   // (8, 512)
    gemm1_kernel<<<grid1, 256>>>(b1);

    dim3 grid2(NOUT / 128, T_TOK / 128);  // (2, 512)
    gemm2_kernel<<<grid2, 256>>>(w2, b2, out);
}

// round 3
// speedup vs baseline: 2.7241x; 2.7241x over previous
#include <cuda_runtime.h>
#include <cuda_bf16.h>
#include <math.h>
#include <stdint.h>

#define T_TOK 65536      // B * (H/2) * (W/2)
#define K_REAL 1156      // (256 + 32 + 1) * 4
#define KP2 1216         // padded to 38 * 32
#define HID 1024
#define NOUT 256
#define CSL2 (KP2 / 4)   // 304 channel slots

// ---------------- scratch (device globals; allocation-free) ----------------
__device__ __align__(16) __nv_bfloat16 g_Phi[(size_t)T_TOK * KP2];
__device__ __align__(16) __nv_bfloat16 g_Plo[(size_t)T_TOK * KP2];
__device__ __align__(16) __nv_bfloat16 g_W1hi[HID * KP2];
__device__ __align__(16) __nv_bfloat16 g_W1lo[HID * KP2];
__device__ __align__(16) __nv_bfloat16 g_W2hi[NOUT * HID];
__device__ __align__(16) __nv_bfloat16 g_W2lo[NOUT * HID];
__device__ __align__(16) __nv_bfloat16 g_Hhi[(size_t)T_TOK * HID];
__device__ __align__(16) __nv_bfloat16 g_Hlo[(size_t)T_TOK * HID];
__device__ float g_cos[2][16][16][128];   // [axis][b][freq][pixel]

// ---------------- PTX helpers (baseline PTX only; NO tcgen05) ----------------
__device__ __forceinline__ uint32_t smem_u32(const void* p) {
    uint32_t a;
    asm("{ .reg .u64 t; cvta.to.shared.u64 t, %1; cvt.u32.u64 %0, t; }"
        : "=r"(a) : "l"(p));
    return a;
}
__device__ __forceinline__ void cp_async16(uint32_t dst, const void* src) {
    asm volatile("cp.async.cg.shared.global [%0], [%1], 16;"
                 :: "r"(dst), "l"(src));
}
#define CP_COMMIT() asm volatile("cp.async.commit_group;" ::: "memory")
#define CP_WAIT(n)  asm volatile("cp.async.wait_group %0;" :: "n"(n) : "memory")

__device__ __forceinline__ void ldsm_x4(uint32_t* r, uint32_t addr) {
    asm volatile("ldmatrix.sync.aligned.m8n8.x4.shared.b16 {%0,%1,%2,%3}, [%4];"
                 : "=r"(r[0]), "=r"(r[1]), "=r"(r[2]), "=r"(r[3]) : "r"(addr));
}
__device__ __forceinline__ void mma_bf16(float* d, const uint32_t* a,
                                         uint32_t b0, uint32_t b1) {
    asm volatile("mma.sync.aligned.m16n8k16.row.col.f32.bf16.bf16.f32 "
                 "{%0,%1,%2,%3}, {%4,%5,%6,%7}, {%8,%9}, {%0,%1,%2,%3};"
                 : "+f"(d[0]), "+f"(d[1]), "+f"(d[2]), "+f"(d[3])
                 : "r"(a[0]), "r"(a[1]), "r"(a[2]), "r"(a[3]), "r"(b0), "r"(b1));
}

// ---------------------------------------------------------------------------
// Setup kernel A: cos tables. arg chain bit-exact to reference fp32 ops.
// ---------------------------------------------------------------------------
__global__ void cos_table_kernel(const float* __restrict__ pos) {
    int idx = blockIdx.x * blockDim.x + threadIdx.x;
    if (idx >= 2 * 16 * 16 * 128) return;
    int w = idx & 127;
    int f = (idx >> 7) & 15;
    int b = (idx >> 11) & 15;
    int ax = idx >> 15;
    const float HALF_PI = 1.57079632679489661923f;
    float pw = pos[b * 4 + 3];
    float stdv = __fdiv_rn(0.1f, fminf(fmaxf(pw, 0.0078125f), 0.5f));
    float ctr = fminf(fmaxf(pos[b * 4 + (ax ? 1 : 0)], -1.f), 1.f);
    float g = __fsub_rn(__fmul_rn(__fdiv_rn((float)w, 127.0f), 2.0f), 1.0f);
    float fs = (float)(1 << f);
    float a = __fmul_rn(__fmul_rn(__fmul_rn(__fsub_rn(g, ctr), stdv), HALF_PI), fs);
    g_cos[ax][b][f][w] = (float)cos((double)a);
}

// ---------------------------------------------------------------------------
// Setup kernel B: split weights (fp32 -> bf16 hi/lo), zero-pad K.
// ---------------------------------------------------------------------------
__global__ void split_w_kernel(const float* __restrict__ w,
                               __nv_bfloat16* __restrict__ hi,
                               __nv_bfloat16* __restrict__ lo,
                               int kreal, int kpad, int total) {
    int idx = blockIdx.x * blockDim.x + threadIdx.x;
    if (idx >= total) return;
    int n = idx / kpad;
    int k = idx - n * kpad;
    float v = (k < kreal) ? w[n * kreal + k] : 0.0f;
    __nv_bfloat16 h = __float2bfloat16(v);
    hi[idx] = h;
    lo[idx] = __float2bfloat16(v - __bfloat162float(h));
}

// ---------------------------------------------------------------------------
// Setup kernel C: build patchified P as bf16 hi/lo [65536 x 1216].
// ---------------------------------------------------------------------------
__global__ void build_p_kernel(const float* __restrict__ gestalt,
                               const float* __restrict__ mask,
                               const float* __restrict__ depth) {
    int idx = blockIdx.x * blockDim.x + threadIdx.x;
    if (idx >= T_TOK * CSL2) return;
    int t = idx / CSL2;
    int c = idx - t * CSL2;

    int b = t >> 12;
    int rem = t & 4095;
    int i = rem >> 6;
    int j = rem & 63;

    float v[4];
    if (c >= 289) {
        v[0] = v[1] = v[2] = v[3] = 0.0f;
    } else {
        int pbase = b * 16384 + (i * 2) * 128 + (j * 2);
        float m00 = mask[pbase];
        float m01 = mask[pbase + 1];
        float m10 = mask[pbase + 128];
        float m11 = mask[pbase + 129];
        if (c < 256) {
            float g = gestalt[b * 256 + c];
            v[0] = g * m00; v[1] = g * m01; v[2] = g * m10; v[3] = g * m11;
        } else if (c < 288) {
            int e = c - 256;
            int f = e >> 1;
            if ((e & 1) == 0) {
                float c0 = g_cos[0][b][f][2 * j];
                float c1 = g_cos[0][b][f][2 * j + 1];
                v[0] = c0 * m00; v[1] = c1 * m01; v[2] = c0 * m10; v[3] = c1 * m11;
            } else {
                float c0 = g_cos[1][b][f][2 * i];
                float c1 = g_cos[1][b][f][2 * i + 1];
                v[0] = c0 * m00; v[1] = c0 * m01; v[2] = c1 * m10; v[3] = c1 * m11;
            }
        } else {
            v[0] = depth[pbase] * m00;
            v[1] = depth[pbase + 1] * m01;
            v[2] = depth[pbase + 128] * m10;
            v[3] = depth[pbase + 129] * m11;
        }
    }
    union { __nv_bfloat16 h[4]; uint2 u; } H, L;
#pragma unroll
    for (int k = 0; k < 4; k++) {
        __nv_bfloat16 hh = __float2bfloat16(v[k]);
        H.h[k] = hh;
        L.h[k] = __float2bfloat16(v[k] - __bfloat162float(hh));
    }
    size_t off = (size_t)t * KP2 + c * 4;
    *(uint2*)(g_Phi + off) = H.u;
    *(uint2*)(g_Plo + off) = L.u;
}

// ---------------------------------------------------------------------------
// bf16x3 GEMM via mma.sync (legacy HMMA): C[M,N] = A[M,K] * B[N,K]^T
// CTA tile 128x128, BK=32, 8 warps (4M x 2N), warp tile 32x64.
// Double-buffered cp.async; padded-row smem (40 elems) for conflict-free ldsm.
// EPI=0: SiLU(x+bias) -> g_Hhi/g_Hlo.  EPI=1: x+bias -> (B,256,64,64) out.
// ---------------------------------------------------------------------------
#define BM 128
#define BN 128
#define BK 32
#define ROWB 80               // row stride bytes (40 bf16)
#define TILE_B (BM * ROWB)    // 10240
#define OFF_AHI 0
#define OFF_ALO TILE_B
#define OFF_BHI (2 * TILE_B)
#define OFF_BLO (3 * TILE_B)
#define STAGE_B (4 * TILE_B)  // 40960
#define SMEM_DYN (2 * STAGE_B)

__device__ __forceinline__ void cp_chunk(uint32_t st,
                                         const __nv_bfloat16* Ah, const __nv_bfloat16* Al,
                                         const __nv_bfloat16* Bh, const __nv_bfloat16* Bl,
                                         int K, int k0, int tid) {
#pragma unroll
    for (int it = 0; it < 2; it++) {
        int idx = tid + it * 256;     // 512 segments of 16B per matrix
        int r = idx >> 2, q = idx & 3;
        uint32_t o = (uint32_t)(r * ROWB + q * 16);
        size_t so = (size_t)r * K + k0 + q * 8;
        cp_async16(st + OFF_AHI + o, Ah + so);
        cp_async16(st + OFF_ALO + o, Al + so);
        cp_async16(st + OFF_BHI + o, Bh + so);
        cp_async16(st + OFF_BLO + o, Bl + so);
    }
}

template <int EPI>
__global__ __launch_bounds__(256, 2) void gemm_bf16x3(
    const __nv_bfloat16* __restrict__ Ahi, const __nv_bfloat16* __restrict__ Alo,
    const __nv_bfloat16* __restrict__ Bhi, const __nv_bfloat16* __restrict__ Blo,
    int K, int NCH, const float* __restrict__ bias, float* __restrict__ outp) {
    extern __shared__ char dsm[];
    uint32_t sb = smem_u32(dsm);

    const int tid = threadIdx.x;
    const int wid = tid >> 5;
    const int L = tid & 31;
    const int m0 = blockIdx.y * BM;
    const int n0 = blockIdx.x * BN;
    const int warp_m = (wid >> 1) * 32;
    const int warp_n = (wid & 1) * 64;

    const __nv_bfloat16* Ah = Ahi + (size_t)m0 * K;
    const __nv_bfloat16* Al = Alo + (size_t)m0 * K;
    const __nv_bfloat16* Bh = Bhi + (size_t)n0 * K;
    const __nv_bfloat16* Bl = Blo + (size_t)n0 * K;

    // per-lane ldmatrix row/col (ldmatrix x4 group = L>>3)
    const int rowA = warp_m + (L & 7) + ((L >> 3) & 1) * 8;  // +mt*16
    const int colA = (L >> 4) * 8;                           // +ks*16
    const int rowB = warp_n + (L & 7) + (L >> 4) * 8;        // +np*16
    const int colB = ((L >> 3) & 1) * 8;                     // +ks*16

    float d[2][8][4];
#pragma unroll
    for (int i = 0; i < 2; i++)
#pragma unroll
        for (int j = 0; j < 8; j++)
#pragma unroll
            for (int e = 0; e < 4; e++) d[i][j][e] = 0.0f;

    cp_chunk(sb, Ah, Al, Bh, Bl, K, 0, tid);
    CP_COMMIT();

    for (int c = 0; c < NCH; c++) {
        CP_WAIT(0);
        __syncthreads();
        if (c + 1 < NCH) {
            cp_chunk(sb + ((c + 1) & 1) * STAGE_B, Ah, Al, Bh, Bl, K,
                     (c + 1) * BK, tid);
            CP_COMMIT();
        }
        uint32_t st = sb + (c & 1) * STAGE_B;
#pragma unroll
        for (int ks = 0; ks < 2; ks++) {
            uint32_t aoff = (uint32_t)((ks * 16 + colA) * 2);
            uint32_t boff = (uint32_t)((ks * 16 + colB) * 2);
            uint32_t ah[2][4], al[2][4];
#pragma unroll
            for (int mt = 0; mt < 2; mt++) {
                uint32_t ra = st + (uint32_t)((rowA + mt * 16) * ROWB) + aoff;
                ldsm_x4(ah[mt], ra + OFF_AHI);
                ldsm_x4(al[mt], ra + OFF_ALO);
            }
            {
                uint32_t bh[4][4];
#pragma unroll
                for (int np = 0; np < 4; np++)
                    ldsm_x4(bh[np], st + OFF_BHI + (uint32_t)((rowB + np * 16) * ROWB) + boff);
#pragma unroll
                for (int mt = 0; mt < 2; mt++)
#pragma unroll
                    for (int np = 0; np < 4; np++) {
                        mma_bf16(d[mt][np * 2],     ah[mt], bh[np][0], bh[np][1]);
                        mma_bf16(d[mt][np * 2 + 1], ah[mt], bh[np][2], bh[np][3]);
                    }
#pragma unroll
                for (int mt = 0; mt < 2; mt++)
#pragma unroll
                    for (int np = 0; np < 4; np++) {
                        mma_bf16(d[mt][np * 2],     al[mt], bh[np][0], bh[np][1]);
                        mma_bf16(d[mt][np * 2 + 1], al[mt], bh[np][2], bh[np][3]);
                    }
            }
            {
                uint32_t bl[4][4];
#pragma unroll
                for (int np = 0; np < 4; np++)
                    ldsm_x4(bl[np], st + OFF_BLO + (uint32_t)((rowB + np * 16) * ROWB) + boff);
#pragma unroll
                for (int mt = 0; mt < 2; mt++)
#pragma unroll
                    for (int np = 0; np < 4; np++) {
                        mma_bf16(d[mt][np * 2],     ah[mt], bl[np][0], bl[np][1]);
                        mma_bf16(d[mt][np * 2 + 1], ah[mt], bl[np][2], bl[np][3]);
                    }
            }
        }
    }

    // ---------------- epilogue ----------------
#pragma unroll
    for (int mt = 0; mt < 2; mt++) {
#pragma unroll
        for (int np = 0; np < 4; np++) {
#pragma unroll
            for (int o = 0; o < 2; o++) {
                const float* dd = d[mt][np * 2 + o];
                int nb = n0 + warp_n + np * 16 + o * 8 + 2 * (L & 3);
                float bv0 = __ldg(bias + nb);
                float bv1 = __ldg(bias + nb + 1);
#pragma unroll
                for (int h = 0; h < 2; h++) {
                    int m = m0 + warp_m + mt * 16 + (L >> 2) + h * 8;
                    float v0 = dd[2 * h] + bv0;
                    float v1 = dd[2 * h + 1] + bv1;
                    if (EPI == 0) {
                        v0 = v0 / (1.0f + expf(-v0));
                        v1 = v1 / (1.0f + expf(-v1));
                        union { __nv_bfloat16 hh[2]; uint32_t u; } HP, LP;
                        __nv_bfloat16 h0 = __float2bfloat16(v0);
                        __nv_bfloat16 h1 = __float2bfloat16(v1);
                        HP.hh[0] = h0; HP.hh[1] = h1;
                        LP.hh[0] = __float2bfloat16(v0 - __bfloat162float(h0));
                        LP.hh[1] = __float2bfloat16(v1 - __bfloat162float(h1));
                        size_t off = (size_t)m * HID + nb;
                        *(uint32_t*)(g_Hhi + off) = HP.u;
                        *(uint32_t*)(g_Hlo + off) = LP.u;
                    } else {
                        size_t obase = ((size_t)(m >> 12) << 20) + (size_t)(m & 4095);
                        outp[obase + ((size_t)nb << 12)] = v0;
                        outp[obase + ((size_t)(nb + 1) << 12)] = v1;
                    }
                }
            }
        }
    }
}

// ---------------------------------------------------------------------------
extern "C" void kernel_launch(void* const* d_in, const int* in_sizes, int n_in,
                              void* d_out, int out_size) {
    const float* position = (const float*)d_in[0];
    const float* gestalt  = (const float*)d_in[1];
    const float* mask     = (const float*)d_in[2];
    const float* depth    = (const float*)d_in[3];
    const float* w1       = (const float*)d_in[4];
    const float* b1       = (const float*)d_in[5];
    const float* w2       = (const float*)d_in[6];
    const float* b2       = (const float*)d_in[7];
    float* out = (float*)d_out;
    (void)in_sizes; (void)n_in; (void)out_size;

    cudaFuncSetAttribute(gemm_bf16x3<0>, cudaFuncAttributeMaxDynamicSharedMemorySize, SMEM_DYN);
    cudaFuncSetAttribute(gemm_bf16x3<1>, cudaFuncAttributeMaxDynamicSharedMemorySize, SMEM_DYN);

    cos_table_kernel<<<(2 * 16 * 16 * 128 + 255) / 256, 256>>>(position);

    __nv_bfloat16 *w1hi, *w1lo, *w2hi, *w2lo, *phi, *plo, *hhi, *hlo;
    cudaGetSymbolAddress((void**)&w1hi, g_W1hi);
    cudaGetSymbolAddress((void**)&w1lo, g_W1lo);
    cudaGetSymbolAddress((void**)&w2hi, g_W2hi);
    cudaGetSymbolAddress((void**)&w2lo, g_W2lo);
    cudaGetSymbolAddress((void**)&phi, g_Phi);
    cudaGetSymbolAddress((void**)&plo, g_Plo);
    cudaGetSymbolAddress((void**)&hhi, g_Hhi);
    cudaGetSymbolAddress((void**)&hlo, g_Hlo);

    split_w_kernel<<<(HID * KP2 + 255) / 256, 256>>>(w1, w1hi, w1lo, K_REAL, KP2, HID * KP2);
    split_w_kernel<<<(NOUT * HID + 255) / 256, 256>>>(w2, w2hi, w2lo, HID, HID, NOUT * HID);

    build_p_kernel<<<(T_TOK * CSL2 + 255) / 256, 256>>>(gestalt, mask, depth);

    dim3 grid1(HID / BN, T_TOK / BM);   // (8, 512)
    gemm_bf16x3<0><<<grid1, 256, SMEM_DYN>>>(phi, plo, w1hi, w1lo, KP2, KP2 / BK, b1, nullptr);

    dim3 grid2(NOUT / BN, T_TOK / BM);  // (2, 512)
    gemm_bf16x3<1><<<grid2, 256, SMEM_DYN>>>(hhi, hlo, w2hi, w2lo, HID, HID / BK, b2, out);
}

// round 4
// speedup vs baseline: 7.9226x; 2.9084x over previous
#include <cuda_runtime.h>
#include <cuda_bf16.h>
#include <math.h>
#include <stdint.h>

#define T_TOK 65536      // B * (H/2) * (W/2)
#define K_REAL 1156
#define HID 1024
#define NOUT 256

// ---------------- scratch (device globals; allocation-free) ----------------
__device__ __align__(16) __nv_bfloat16 g_Hhi[(size_t)T_TOK * HID];
__device__ __align__(16) __nv_bfloat16 g_Hlo[(size_t)T_TOK * HID];
__device__ __align__(16) __nv_bfloat16 g_W2hi[NOUT * HID];
__device__ __align__(16) __nv_bfloat16 g_W2lo[NOUT * HID];
__device__ float g_cos[2][16][16][128];          // [axis][b][freq][pixel]
__device__ __align__(16) float g_U[16 * 4 * HID];        // [b][s][n]
__device__ __align__(16) float g_CX[16 * 4 * 64 * HID];  // [b][s][j][n]
__device__ __align__(16) float g_CY[16 * 4 * 64 * HID];  // [b][s][i][n]

// ---------------- PTX helpers (baseline PTX only) ----------------
__device__ __forceinline__ uint32_t smem_u32(const void* p) {
    uint32_t a;
    asm("{ .reg .u64 t; cvta.to.shared.u64 t, %1; cvt.u32.u64 %0, t; }"
        : "=r"(a) : "l"(p));
    return a;
}
__device__ __forceinline__ void cp_async16(uint32_t dst, const void* src) {
    asm volatile("cp.async.cg.shared.global [%0], [%1], 16;"
                 :: "r"(dst), "l"(src));
}
#define CP_COMMIT() asm volatile("cp.async.commit_group;" ::: "memory")
#define CP_WAIT(n)  asm volatile("cp.async.wait_group %0;" :: "n"(n) : "memory")

__device__ __forceinline__ void ldsm_x4(uint32_t* r, uint32_t addr) {
    asm volatile("ldmatrix.sync.aligned.m8n8.x4.shared.b16 {%0,%1,%2,%3}, [%4];"
                 : "=r"(r[0]), "=r"(r[1]), "=r"(r[2]), "=r"(r[3]) : "r"(addr));
}
__device__ __forceinline__ void mma_bf16(float* d, const uint32_t* a,
                                         uint32_t b0, uint32_t b1) {
    asm volatile("mma.sync.aligned.m16n8k16.row.col.f32.bf16.bf16.f32 "
                 "{%0,%1,%2,%3}, {%4,%5,%6,%7}, {%8,%9}, {%0,%1,%2,%3};"
                 : "+f"(d[0]), "+f"(d[1]), "+f"(d[2]), "+f"(d[3])
                 : "r"(a[0]), "r"(a[1]), "r"(a[2]), "r"(a[3]), "r"(b0), "r"(b1));
}

// ---------------------------------------------------------------------------
// Setup A: cos tables (arg chain bit-exact to reference fp32 ops).
// ---------------------------------------------------------------------------
__global__ void cos_table_kernel(const float* __restrict__ pos) {
    int idx = blockIdx.x * blockDim.x + threadIdx.x;
    if (idx >= 2 * 16 * 16 * 128) return;
    int w = idx & 127;
    int f = (idx >> 7) & 15;
    int b = (idx >> 11) & 15;
    int ax = idx >> 15;
    const float HALF_PI = 1.57079632679489661923f;
    float pw = pos[b * 4 + 3];
    float stdv = __fdiv_rn(0.1f, fminf(fmaxf(pw, 0.0078125f), 0.5f));
    float ctr = fminf(fmaxf(pos[b * 4 + (ax ? 1 : 0)], -1.f), 1.f);
    float g = __fsub_rn(__fmul_rn(__fdiv_rn((float)w, 127.0f), 2.0f), 1.0f);
    float fs = (float)(1 << f);
    float a = __fmul_rn(__fmul_rn(__fmul_rn(__fsub_rn(g, ctr), stdv), HALF_PI), fs);
    g_cos[ax][b][f][w] = (float)cos((double)a);
}

// ---------------------------------------------------------------------------
// Setup B: U[b][s][n] = sum_c W1[n, 4c+s] * gestalt[b, c]
// ---------------------------------------------------------------------------
__global__ void u_kernel(const float* __restrict__ w1,
                         const float* __restrict__ gestalt) {
    int n = blockIdx.x * 256 + threadIdx.x;     // 0..1023
    int b = blockIdx.y;
    const float4* wrow = (const float4*)(w1 + (size_t)n * K_REAL);
    const float* g = gestalt + b * 256;
    float a0 = 0.f, a1 = 0.f, a2 = 0.f, a3 = 0.f;
#pragma unroll 4
    for (int c = 0; c < 256; c++) {
        float4 w = wrow[c];
        float gv = g[c];
        a0 += w.x * gv; a1 += w.y * gv; a2 += w.z * gv; a3 += w.w * gv;
    }
    g_U[(b * 4 + 0) * HID + n] = a0;
    g_U[(b * 4 + 1) * HID + n] = a1;
    g_U[(b * 4 + 2) * HID + n] = a2;
    g_U[(b * 4 + 3) * HID + n] = a3;
}

// ---------------------------------------------------------------------------
// Setup C: CX[b][s][j][n] = sum_f W1[n, 1024 + 8f + s]     * cos0[b][f][2j+sx]
//          CY[b][s][i][n] = sum_f W1[n, 1028 + 8f + s]     * cos1[b][f][2i+sy]
// ---------------------------------------------------------------------------
__global__ void cxy_kernel(const float* __restrict__ w1) {
    int n = blockIdx.x * 256 + threadIdx.x;
    int s = blockIdx.y;
    int bz = blockIdx.z;
    int b = bz & 15;
    int ax = bz >> 4;
    int sub = ax ? (s >> 1) : (s & 1);   // sy for y-axis, sx for x-axis
    float w[16];
    size_t base = (size_t)n * K_REAL + 1024 + (ax ? 4 : 0) + s;
#pragma unroll
    for (int f = 0; f < 16; f++) w[f] = w1[base + 8 * f];
    float* outp = (ax ? g_CY : g_CX) + ((size_t)(b * 4 + s) * 64) * HID + n;
    const float* crow = &g_cos[ax][b][0][0];   // [16][128]
#pragma unroll 2
    for (int j = 0; j < 64; j++) {
        float acc = 0.f;
#pragma unroll
        for (int f = 0; f < 16; f++) acc += w[f] * crow[f * 128 + 2 * j + sub];
        outp[(size_t)j * HID] = acc;
    }
}

// ---------------------------------------------------------------------------
// Setup D: split W2 (fp32 -> bf16 hi/lo).
// ---------------------------------------------------------------------------
__global__ void split_w_kernel(const float* __restrict__ w,
                               __nv_bfloat16* __restrict__ hi,
                               __nv_bfloat16* __restrict__ lo, int total) {
    int idx = blockIdx.x * blockDim.x + threadIdx.x;
    if (idx >= total) return;
    float v = w[idx];
    __nv_bfloat16 h = __float2bfloat16(v);
    hi[idx] = h;
    lo[idx] = __float2bfloat16(v - __bfloat162float(h));
}

// ---------------------------------------------------------------------------
// Fused H: h[t,n] = b1[n] + sum_s m_s * (U + CX[j] + CY[i] + d_s*Wd) ;
// SiLU; split to bf16 hi/lo -> g_Hhi/g_Hlo. Replaces GEMM1 entirely.
// Grid (32 ngroups of 32 n, 16 b), 256 threads.
// ---------------------------------------------------------------------------
#define FH_SMEM (16672 * 4)

__global__ __launch_bounds__(256) void fused_h_kernel(
    const float* __restrict__ mask, const float* __restrict__ depth,
    const float* __restrict__ w1, const float* __restrict__ b1) {
    extern __shared__ float sm[];
    float* sCX = sm;             // [s][j][nl]  4*64*32
    float* sCY = sm + 8192;      // [s][i][nl]
    float* sU  = sm + 16384;     // [s][nl]
    float* sWd = sm + 16512;     // [s][nl]
    float* sB  = sm + 16640;     // [nl]

    const int b  = blockIdx.y;
    const int n0 = blockIdx.x * 32;
    const int tid = threadIdx.x;

    for (int idx = tid; idx < 8192; idx += 256) {
        int nl = idx & 31, j = (idx >> 5) & 63, s = idx >> 11;
        size_t go = ((size_t)(b * 4 + s) * 64 + j) * HID + n0 + nl;
        sCX[idx] = g_CX[go];
        sCY[idx] = g_CY[go];
    }
    if (tid < 128) {
        int s = tid >> 5, nl = tid & 31;
        sU[tid]  = g_U[(b * 4 + s) * HID + n0 + nl];
        sWd[tid] = w1[(size_t)(n0 + nl) * K_REAL + 1152 + s];
    }
    if (tid < 32) sB[tid] = b1[n0 + tid];
    __syncthreads();

    const int npl = (tid & 15) * 2;   // n-pair
    const int tg  = tid >> 4;         // 16 groups, each 4 i-values

    float2 u[4], wd[4], bb;
#pragma unroll
    for (int s = 0; s < 4; s++) {
        u[s]  = *(float2*)&sU[s * 32 + npl];
        wd[s] = *(float2*)&sWd[s * 32 + npl];
    }
    bb = *(float2*)&sB[npl];

#pragma unroll 1
    for (int ib = 0; ib < 4; ib++) {
        int i = tg * 4 + ib;
        float2 cy[4];
#pragma unroll
        for (int s = 0; s < 4; s++) cy[s] = *(float2*)&sCY[s * 2048 + i * 32 + npl];
        const float* mrow = mask  + b * 16384 + i * 256;
        const float* drow = depth + b * 16384 + i * 256;
        size_t rowbase = ((size_t)(b * 4096 + i * 64)) * HID + n0 + npl;
#pragma unroll 1
        for (int j = 0; j < 64; j++) {
            float m00 = mrow[2 * j],       m01 = mrow[2 * j + 1];
            float m10 = mrow[2 * j + 128], m11 = mrow[2 * j + 129];
            float d00 = drow[2 * j],       d01 = drow[2 * j + 1];
            float d10 = drow[2 * j + 128], d11 = drow[2 * j + 129];
            float2 cx0 = *(float2*)&sCX[0 * 2048 + j * 32 + npl];
            float2 cx1 = *(float2*)&sCX[1 * 2048 + j * 32 + npl];
            float2 cx2 = *(float2*)&sCX[2 * 2048 + j * 32 + npl];
            float2 cx3 = *(float2*)&sCX[3 * 2048 + j * 32 + npl];

            union { __nv_bfloat16 h2[2]; uint32_t uu; } HP, LP;
#pragma unroll
            for (int q = 0; q < 2; q++) {
                float c0 = (q ? u[0].y + cx0.y + cy[0].y : u[0].x + cx0.x + cy[0].x);
                float c1 = (q ? u[1].y + cx1.y + cy[1].y : u[1].x + cx1.x + cy[1].x);
                float c2 = (q ? u[2].y + cx2.y + cy[2].y : u[2].x + cx2.x + cy[2].x);
                float c3 = (q ? u[3].y + cx3.y + cy[3].y : u[3].x + cx3.x + cy[3].x);
                float w0 = (q ? wd[0].y : wd[0].x);
                float w1v = (q ? wd[1].y : wd[1].x);
                float w2v = (q ? wd[2].y : wd[2].x);
                float w3 = (q ? wd[3].y : wd[3].x);
                float h = (q ? bb.y : bb.x);
                h += m00 * (c0 + d00 * w0);
                h += m01 * (c1 + d01 * w1v);
                h += m10 * (c2 + d10 * w2v);
                h += m11 * (c3 + d11 * w3);
                float v = h / (1.0f + expf(-h));
                __nv_bfloat16 hh = __float2bfloat16(v);
                HP.h2[q] = hh;
                LP.h2[q] = __float2bfloat16(v - __bfloat162float(hh));
            }
            size_t off = rowbase + (size_t)j * HID;
            *(uint32_t*)(g_Hhi + off) = HP.uu;
            *(uint32_t*)(g_Hlo + off) = LP.uu;
        }
    }
}

// ---------------------------------------------------------------------------
// bf16x3 GEMM via mma.sync (verified in R3): C = A * B^T, +bias, scatter out.
// CTA 128x128, BK=32, 8 warps (4Mx2N), double-buffered cp.async.
// ---------------------------------------------------------------------------
#define BM 128
#define BN 128
#define BK 32
#define ROWB 80
#define TILE_B (BM * ROWB)
#define OFF_AHI 0
#define OFF_ALO TILE_B
#define OFF_BHI (2 * TILE_B)
#define OFF_BLO (3 * TILE_B)
#define STAGE_B (4 * TILE_B)
#define SMEM_DYN (2 * STAGE_B)

__device__ __forceinline__ void cp_chunk(uint32_t st,
                                         const __nv_bfloat16* Ah, const __nv_bfloat16* Al,
                                         const __nv_bfloat16* Bh, const __nv_bfloat16* Bl,
                                         int K, int k0, int tid) {
#pragma unroll
    for (int it = 0; it < 2; it++) {
        int idx = tid + it * 256;
        int r = idx >> 2, q = idx & 3;
        uint32_t o = (uint32_t)(r * ROWB + q * 16);
        size_t so = (size_t)r * K + k0 + q * 8;
        cp_async16(st + OFF_AHI + o, Ah + so);
        cp_async16(st + OFF_ALO + o, Al + so);
        cp_async16(st + OFF_BHI + o, Bh + so);
        cp_async16(st + OFF_BLO + o, Bl + so);
    }
}

__global__ __launch_bounds__(256, 2) void gemm2_bf16x3(
    const __nv_bfloat16* __restrict__ Ahi, const __nv_bfloat16* __restrict__ Alo,
    const __nv_bfloat16* __restrict__ Bhi, const __nv_bfloat16* __restrict__ Blo,
    int K, int NCH, const float* __restrict__ bias, float* __restrict__ outp) {
    extern __shared__ char dsm[];
    uint32_t sb = smem_u32(dsm);

    const int tid = threadIdx.x;
    const int wid = tid >> 5;
    const int L = tid & 31;
    const int m0 = blockIdx.y * BM;
    const int n0 = blockIdx.x * BN;
    const int warp_m = (wid >> 1) * 32;
    const int warp_n = (wid & 1) * 64;

    const __nv_bfloat16* Ah = Ahi + (size_t)m0 * K;
    const __nv_bfloat16* Al = Alo + (size_t)m0 * K;
    const __nv_bfloat16* Bh = Bhi + (size_t)n0 * K;
    const __nv_bfloat16* Bl = Blo + (size_t)n0 * K;

    const int rowA = warp_m + (L & 7) + ((L >> 3) & 1) * 8;
    const int colA = (L >> 4) * 8;
    const int rowB = warp_n + (L & 7) + (L >> 4) * 8;
    const int colB = ((L >> 3) & 1) * 8;

    float d[2][8][4];
#pragma unroll
    for (int i = 0; i < 2; i++)
#pragma unroll
        for (int j = 0; j < 8; j++)
#pragma unroll
            for (int e = 0; e < 4; e++) d[i][j][e] = 0.0f;

    cp_chunk(sb, Ah, Al, Bh, Bl, K, 0, tid);
    CP_COMMIT();

    for (int c = 0; c < NCH; c++) {
        CP_WAIT(0);
        __syncthreads();
        if (c + 1 < NCH) {
            cp_chunk(sb + ((c + 1) & 1) * STAGE_B, Ah, Al, Bh, Bl, K,
                     (c + 1) * BK, tid);
            CP_COMMIT();
        }
        uint32_t st = sb + (c & 1) * STAGE_B;
#pragma unroll
        for (int ks = 0; ks < 2; ks++) {
            uint32_t aoff = (uint32_t)((ks * 16 + colA) * 2);
            uint32_t boff = (uint32_t)((ks * 16 + colB) * 2);
            uint32_t ah[2][4], al[2][4];
#pragma unroll
            for (int mt = 0; mt < 2; mt++) {
                uint32_t ra = st + (uint32_t)((rowA + mt * 16) * ROWB) + aoff;
                ldsm_x4(ah[mt], ra + OFF_AHI);
                ldsm_x4(al[mt], ra + OFF_ALO);
            }
            {
                uint32_t bh[4][4];
#pragma unroll
                for (int np = 0; np < 4; np++)
                    ldsm_x4(bh[np], st + OFF_BHI + (uint32_t)((rowB + np * 16) * ROWB) + boff);
#pragma unroll
                for (int mt = 0; mt < 2; mt++)
#pragma unroll
                    for (int np = 0; np < 4; np++) {
                        mma_bf16(d[mt][np * 2],     ah[mt], bh[np][0], bh[np][1]);
                        mma_bf16(d[mt][np * 2 + 1], ah[mt], bh[np][2], bh[np][3]);
                    }
#pragma unroll
                for (int mt = 0; mt < 2; mt++)
#pragma unroll
                    for (int np = 0; np < 4; np++) {
                        mma_bf16(d[mt][np * 2],     al[mt], bh[np][0], bh[np][1]);
                        mma_bf16(d[mt][np * 2 + 1], al[mt], bh[np][2], bh[np][3]);
                    }
            }
            {
                uint32_t bl[4][4];
#pragma unroll
                for (int np = 0; np < 4; np++)
                    ldsm_x4(bl[np], st + OFF_BLO + (uint32_t)((rowB + np * 16) * ROWB) + boff);
#pragma unroll
                for (int mt = 0; mt < 2; mt++)
#pragma unroll
                    for (int np = 0; np < 4; np++) {
                        mma_bf16(d[mt][np * 2],     ah[mt], bl[np][0], bl[np][1]);
                        mma_bf16(d[mt][np * 2 + 1], ah[mt], bl[np][2], bl[np][3]);
                    }
            }
        }
    }

#pragma unroll
    for (int mt = 0; mt < 2; mt++) {
#pragma unroll
        for (int np = 0; np < 4; np++) {
#pragma unroll
            for (int o = 0; o < 2; o++) {
                const float* dd = d[mt][np * 2 + o];
                int nb = n0 + warp_n + np * 16 + o * 8 + 2 * (L & 3);
                float bv0 = __ldg(bias + nb);
                float bv1 = __ldg(bias + nb + 1);
#pragma unroll
                for (int h = 0; h < 2; h++) {
                    int m = m0 + warp_m + mt * 16 + (L >> 2) + h * 8;
                    size_t obase = ((size_t)(m >> 12) << 20) + (size_t)(m & 4095);
                    outp[obase + ((size_t)nb << 12)] = dd[2 * h] + bv0;
                    outp[obase + ((size_t)(nb + 1) << 12)] = dd[2 * h + 1] + bv1;
                }
            }
        }
    }
}

// ---------------------------------------------------------------------------
extern "C" void kernel_launch(void* const* d_in, const int* in_sizes, int n_in,
                              void* d_out, int out_size) {
    const float* position = (const float*)d_in[0];
    const float* gestalt  = (const float*)d_in[1];
    const float* mask     = (const float*)d_in[2];
    const float* depth    = (const float*)d_in[3];
    const float* w1       = (const float*)d_in[4];
    const float* b1       = (const float*)d_in[5];
    const float* w2       = (const float*)d_in[6];
    const float* b2       = (const float*)d_in[7];
    float* out = (float*)d_out;
    (void)in_sizes; (void)n_in; (void)out_size;

    cudaFuncSetAttribute(gemm2_bf16x3, cudaFuncAttributeMaxDynamicSharedMemorySize, SMEM_DYN);
    cudaFuncSetAttribute(fused_h_kernel, cudaFuncAttributeMaxDynamicSharedMemorySize, FH_SMEM);

    __nv_bfloat16 *w2hi, *w2lo, *hhi, *hlo;
    cudaGetSymbolAddress((void**)&w2hi, g_W2hi);
    cudaGetSymbolAddress((void**)&w2lo, g_W2lo);
    cudaGetSymbolAddress((void**)&hhi, g_Hhi);
    cudaGetSymbolAddress((void**)&hlo, g_Hlo);

    cos_table_kernel<<<(2 * 16 * 16 * 128 + 255) / 256, 256>>>(position);
    u_kernel<<<dim3(4, 16), 256>>>(w1, gestalt);
    cxy_kernel<<<dim3(4, 4, 32), 256>>>(w1);
    split_w_kernel<<<(NOUT * HID + 255) / 256, 256>>>(w2, w2hi, w2lo, NOUT * HID);

    fused_h_kernel<<<dim3(32, 16), 256, FH_SMEM>>>(mask, depth, w1, b1);

    dim3 grid2(NOUT / BN, T_TOK / BM);  // (2, 512)
    gemm2_bf16x3<<<grid2, 256, SMEM_DYN>>>(hhi, hlo, w2hi, w2lo, HID, HID / BK, b2, out);
}

// round 5
// speedup vs baseline: 7.9754x; 1.0067x over previous
#include <cuda_runtime.h>
#include <cuda_bf16.h>
#include <math.h>
#include <stdint.h>

#define T_TOK 65536      // B * (H/2) * (W/2)
#define K_REAL 1156
#define HID 1024
#define NOUT 256

// ---------------- scratch (device globals; allocation-free) ----------------
__device__ __align__(16) __nv_bfloat16 g_Hhi[(size_t)T_TOK * HID];
__device__ __align__(16) __nv_bfloat16 g_Hlo[(size_t)T_TOK * HID];
__device__ __align__(16) __nv_bfloat16 g_W2hi[NOUT * HID];
__device__ __align__(16) __nv_bfloat16 g_W2lo[NOUT * HID];
__device__ float g_cos[2][16][16][128];          // [axis][b][freq][pixel]
__device__ __align__(16) float g_U[16 * 4 * HID];        // [b][s][n]
__device__ __align__(16) float g_CX[16 * 4 * 64 * HID];  // [b][s][j][n]
__device__ __align__(16) float g_CY[16 * 4 * 64 * HID];  // [b][s][i][n]

// ---------------- PTX helpers (baseline PTX only) ----------------
__device__ __forceinline__ uint32_t smem_u32(const void* p) {
    uint32_t a;
    asm("{ .reg .u64 t; cvta.to.shared.u64 t, %1; cvt.u32.u64 %0, t; }"
        : "=r"(a) : "l"(p));
    return a;
}
__device__ __forceinline__ void cp_async16(uint32_t dst, const void* src) {
    asm volatile("cp.async.cg.shared.global [%0], [%1], 16;"
                 :: "r"(dst), "l"(src));
}
#define CP_COMMIT() asm volatile("cp.async.commit_group;" ::: "memory")
#define CP_WAIT(n)  asm volatile("cp.async.wait_group %0;" :: "n"(n) : "memory")

__device__ __forceinline__ void ldsm_x4(uint32_t* r, uint32_t addr) {
    asm volatile("ldmatrix.sync.aligned.m8n8.x4.shared.b16 {%0,%1,%2,%3}, [%4];"
                 : "=r"(r[0]), "=r"(r[1]), "=r"(r[2]), "=r"(r[3]) : "r"(addr));
}
__device__ __forceinline__ void mma_bf16(float* d, const uint32_t* a,
                                         uint32_t b0, uint32_t b1) {
    asm volatile("mma.sync.aligned.m16n8k16.row.col.f32.bf16.bf16.f32 "
                 "{%0,%1,%2,%3}, {%4,%5,%6,%7}, {%8,%9}, {%0,%1,%2,%3};"
                 : "+f"(d[0]), "+f"(d[1]), "+f"(d[2]), "+f"(d[3])
                 : "r"(a[0]), "r"(a[1]), "r"(a[2]), "r"(a[3]), "r"(b0), "r"(b1));
}

// ---------------------------------------------------------------------------
// Setup A: cos tables (arg chain bit-exact to reference fp32 ops).
// ---------------------------------------------------------------------------
__global__ void cos_table_kernel(const float* __restrict__ pos) {
    int idx = blockIdx.x * blockDim.x + threadIdx.x;
    if (idx >= 2 * 16 * 16 * 128) return;
    int w = idx & 127;
    int f = (idx >> 7) & 15;
    int b = (idx >> 11) & 15;
    int ax = idx >> 15;
    const float HALF_PI = 1.57079632679489661923f;
    float pw = pos[b * 4 + 3];
    float stdv = __fdiv_rn(0.1f, fminf(fmaxf(pw, 0.0078125f), 0.5f));
    float ctr = fminf(fmaxf(pos[b * 4 + (ax ? 1 : 0)], -1.f), 1.f);
    float g = __fsub_rn(__fmul_rn(__fdiv_rn((float)w, 127.0f), 2.0f), 1.0f);
    float fs = (float)(1 << f);
    float a = __fmul_rn(__fmul_rn(__fmul_rn(__fsub_rn(g, ctr), stdv), HALF_PI), fs);
    g_cos[ax][b][f][w] = (float)cos((double)a);
}

// ---------------------------------------------------------------------------
// Setup B: U[b][s][n] = sum_c W1[n, 4c+s] * gestalt[b, c]
// ---------------------------------------------------------------------------
__global__ void u_kernel(const float* __restrict__ w1,
                         const float* __restrict__ gestalt) {
    int n = blockIdx.x * 256 + threadIdx.x;     // 0..1023
    int b = blockIdx.y;
    const float4* wrow = (const float4*)(w1 + (size_t)n * K_REAL);
    const float* g = gestalt + b * 256;
    float a0 = 0.f, a1 = 0.f, a2 = 0.f, a3 = 0.f;
#pragma unroll 4
    for (int c = 0; c < 256; c++) {
        float4 w = wrow[c];
        float gv = g[c];
        a0 += w.x * gv; a1 += w.y * gv; a2 += w.z * gv; a3 += w.w * gv;
    }
    g_U[(b * 4 + 0) * HID + n] = a0;
    g_U[(b * 4 + 1) * HID + n] = a1;
    g_U[(b * 4 + 2) * HID + n] = a2;
    g_U[(b * 4 + 3) * HID + n] = a3;
}

// ---------------------------------------------------------------------------
// Setup C: CX[b][s][j][n] = sum_f W1[n, 1024 + 8f + s] * cos0[b][f][2j+sx]
//          CY[b][s][i][n] = sum_f W1[n, 1028 + 8f + s] * cos1[b][f][2i+sy]
// ---------------------------------------------------------------------------
__global__ void cxy_kernel(const float* __restrict__ w1) {
    int n = blockIdx.x * 256 + threadIdx.x;
    int s = blockIdx.y;
    int bz = blockIdx.z;
    int b = bz & 15;
    int ax = bz >> 4;
    int sub = ax ? (s >> 1) : (s & 1);   // sy for y-axis, sx for x-axis
    float w[16];
    size_t base = (size_t)n * K_REAL + 1024 + (ax ? 4 : 0) + s;
#pragma unroll
    for (int f = 0; f < 16; f++) w[f] = w1[base + 8 * f];
    float* outp = (ax ? g_CY : g_CX) + ((size_t)(b * 4 + s) * 64) * HID + n;
    const float* crow = &g_cos[ax][b][0][0];   // [16][128]
#pragma unroll 2
    for (int j = 0; j < 64; j++) {
        float acc = 0.f;
#pragma unroll
        for (int f = 0; f < 16; f++) acc += w[f] * crow[f * 128 + 2 * j + sub];
        outp[(size_t)j * HID] = acc;
    }
}

// ---------------------------------------------------------------------------
// Setup D: split W2 (fp32 -> bf16 hi/lo).
// ---------------------------------------------------------------------------
__global__ void split_w_kernel(const float* __restrict__ w,
                               __nv_bfloat16* __restrict__ hi,
                               __nv_bfloat16* __restrict__ lo, int total) {
    int idx = blockIdx.x * blockDim.x + threadIdx.x;
    if (idx >= total) return;
    float v = w[idx];
    __nv_bfloat16 h = __float2bfloat16(v);
    hi[idx] = h;
    lo[idx] = __float2bfloat16(v - __bfloat162float(h));
}

// ---------------------------------------------------------------------------
// Fused H: h[t,n] = b1[n] + sum_s m_s * (U + CX[j] + CY[i] + d_s*Wd) ;
// fast SiLU; split to bf16 hi/lo -> g_Hhi/g_Hlo (streaming stores).
// ---------------------------------------------------------------------------
#define FH_SMEM (16672 * 4)

__global__ __launch_bounds__(256) void fused_h_kernel(
    const float* __restrict__ mask, const float* __restrict__ depth,
    const float* __restrict__ w1, const float* __restrict__ b1) {
    extern __shared__ float sm[];
    float* sCX = sm;             // [s][j][nl]  4*64*32
    float* sCY = sm + 8192;      // [s][i][nl]
    float* sU  = sm + 16384;     // [s][nl]
    float* sWd = sm + 16512;     // [s][nl]
    float* sB  = sm + 16640;     // [nl]

    const int b  = blockIdx.y;
    const int n0 = blockIdx.x * 32;
    const int tid = threadIdx.x;

    for (int idx = tid; idx < 8192; idx += 256) {
        int nl = idx & 31, j = (idx >> 5) & 63, s = idx >> 11;
        size_t go = ((size_t)(b * 4 + s) * 64 + j) * HID + n0 + nl;
        sCX[idx] = g_CX[go];
        sCY[idx] = g_CY[go];
    }
    if (tid < 128) {
        int s = tid >> 5, nl = tid & 31;
        sU[tid]  = g_U[(b * 4 + s) * HID + n0 + nl];
        sWd[tid] = w1[(size_t)(n0 + nl) * K_REAL + 1152 + s];
    }
    if (tid < 32) sB[tid] = b1[n0 + tid];
    __syncthreads();

    const int npl = (tid & 15) * 2;   // n-pair
    const int tg  = tid >> 4;         // 16 groups, each 4 i-values

    float2 u[4], wd[4], bb;
#pragma unroll
    for (int s = 0; s < 4; s++) {
        u[s]  = *(float2*)&sU[s * 32 + npl];
        wd[s] = *(float2*)&sWd[s * 32 + npl];
    }
    bb = *(float2*)&sB[npl];

#pragma unroll 1
    for (int ib = 0; ib < 4; ib++) {
        int i = tg * 4 + ib;
        // fold CY and U into one per-i constant (saves 4 adds/iter)
        float2 uc[4];
#pragma unroll
        for (int s = 0; s < 4; s++) {
            float2 cy = *(float2*)&sCY[s * 2048 + i * 32 + npl];
            uc[s].x = u[s].x + cy.x;
            uc[s].y = u[s].y + cy.y;
        }
        const float* mrow = mask  + b * 16384 + i * 256;
        const float* drow = depth + b * 16384 + i * 256;
        size_t rowbase = ((size_t)(b * 4096 + i * 64)) * HID + n0 + npl;
#pragma unroll 2
        for (int j = 0; j < 64; j++) {
            float m00 = mrow[2 * j],       m01 = mrow[2 * j + 1];
            float m10 = mrow[2 * j + 128], m11 = mrow[2 * j + 129];
            float d00 = drow[2 * j],       d01 = drow[2 * j + 1];
            float d10 = drow[2 * j + 128], d11 = drow[2 * j + 129];
            float2 cx0 = *(float2*)&sCX[0 * 2048 + j * 32 + npl];
            float2 cx1 = *(float2*)&sCX[1 * 2048 + j * 32 + npl];
            float2 cx2 = *(float2*)&sCX[2 * 2048 + j * 32 + npl];
            float2 cx3 = *(float2*)&sCX[3 * 2048 + j * 32 + npl];

            union { __nv_bfloat16 h2[2]; uint32_t uu; } HP, LP;
#pragma unroll
            for (int q = 0; q < 2; q++) {
                float c0 = (q ? uc[0].y + cx0.y : uc[0].x + cx0.x);
                float c1 = (q ? uc[1].y + cx1.y : uc[1].x + cx1.x);
                float c2 = (q ? uc[2].y + cx2.y : uc[2].x + cx2.x);
                float c3 = (q ? uc[3].y + cx3.y : uc[3].x + cx3.x);
                float w0  = (q ? wd[0].y : wd[0].x);
                float w1v = (q ? wd[1].y : wd[1].x);
                float w2v = (q ? wd[2].y : wd[2].x);
                float w3  = (q ? wd[3].y : wd[3].x);
                float h = (q ? bb.y : bb.x);
                h += m00 * (c0 + d00 * w0);
                h += m01 * (c1 + d01 * w1v);
                h += m10 * (c2 + d10 * w2v);
                h += m11 * (c3 + d11 * w3);
                // fast SiLU: h * 1/(1+e^-h) via MUFU (err ~1e-6, below bf16 split)
                float v = h * __frcp_rn(1.0f + __expf(-h));
                __nv_bfloat16 hh = __float2bfloat16(v);
                HP.h2[q] = hh;
                LP.h2[q] = __float2bfloat16(v - __bfloat162float(hh));
            }
            size_t off = rowbase + (size_t)j * HID;
            __stcs((uint32_t*)(g_Hhi + off), HP.uu);
            __stcs((uint32_t*)(g_Hlo + off), LP.uu);
        }
    }
}

// ---------------------------------------------------------------------------
// bf16x3 GEMM via mma.sync (verified): C = A * B^T, +bias, scatter out.
// CTA 128x128, BK=32, 8 warps (4Mx2N), double-buffered cp.async.
// ---------------------------------------------------------------------------
#define BM 128
#define BN 128
#define BK 32
#define ROWB 80
#define TILE_B (BM * ROWB)
#define OFF_AHI 0
#define OFF_ALO TILE_B
#define OFF_BHI (2 * TILE_B)
#define OFF_BLO (3 * TILE_B)
#define STAGE_B (4 * TILE_B)
#define SMEM_DYN (2 * STAGE_B)

__device__ __forceinline__ void cp_chunk(uint32_t st,
                                         const __nv_bfloat16* Ah, const __nv_bfloat16* Al,
                                         const __nv_bfloat16* Bh, const __nv_bfloat16* Bl,
                                         int K, int k0, int tid) {
#pragma unroll
    for (int it = 0; it < 2; it++) {
        int idx = tid + it * 256;
        int r = idx >> 2, q = idx & 3;
        uint32_t o = (uint32_t)(r * ROWB + q * 16);
        size_t so = (size_t)r * K + k0 + q * 8;
        cp_async16(st + OFF_AHI + o, Ah + so);
        cp_async16(st + OFF_ALO + o, Al + so);
        cp_async16(st + OFF_BHI + o, Bh + so);
        cp_async16(st + OFF_BLO + o, Bl + so);
    }
}

__global__ __launch_bounds__(256, 2) void gemm2_bf16x3(
    const __nv_bfloat16* __restrict__ Ahi, const __nv_bfloat16* __restrict__ Alo,
    const __nv_bfloat16* __restrict__ Bhi, const __nv_bfloat16* __restrict__ Blo,
    int K, int NCH, const float* __restrict__ bias, float* __restrict__ outp) {
    extern __shared__ char dsm[];
    uint32_t sb = smem_u32(dsm);

    const int tid = threadIdx.x;
    const int wid = tid >> 5;
    const int L = tid & 31;
    const int m0 = blockIdx.y * BM;
    const int n0 = blockIdx.x * BN;
    const int warp_m = (wid >> 1) * 32;
    const int warp_n = (wid & 1) * 64;

    const __nv_bfloat16* Ah = Ahi + (size_t)m0 * K;
    const __nv_bfloat16* Al = Alo + (size_t)m0 * K;
    const __nv_bfloat16* Bh = Bhi + (size_t)n0 * K;
    const __nv_bfloat16* Bl = Blo + (size_t)n0 * K;

    const int rowA = warp_m + (L & 7) + ((L >> 3) & 1) * 8;
    const int colA = (L >> 4) * 8;
    const int rowB = warp_n + (L & 7) + (L >> 4) * 8;
    const int colB = ((L >> 3) & 1) * 8;

    float d[2][8][4];
#pragma unroll
    for (int i = 0; i < 2; i++)
#pragma unroll
        for (int j = 0; j < 8; j++)
#pragma unroll
            for (int e = 0; e < 4; e++) d[i][j][e] = 0.0f;

    cp_chunk(sb, Ah, Al, Bh, Bl, K, 0, tid);
    CP_COMMIT();

    for (int c = 0; c < NCH; c++) {
        CP_WAIT(0);
        __syncthreads();
        if (c + 1 < NCH) {
            cp_chunk(sb + ((c + 1) & 1) * STAGE_B, Ah, Al, Bh, Bl, K,
                     (c + 1) * BK, tid);
            CP_COMMIT();
        }
        uint32_t st = sb + (c & 1) * STAGE_B;
#pragma unroll
        for (int ks = 0; ks < 2; ks++) {
            uint32_t aoff = (uint32_t)((ks * 16 + colA) * 2);
            uint32_t boff = (uint32_t)((ks * 16 + colB) * 2);
            uint32_t ah[2][4], al[2][4];
#pragma unroll
            for (int mt = 0; mt < 2; mt++) {
                uint32_t ra = st + (uint32_t)((rowA + mt * 16) * ROWB) + aoff;
                ldsm_x4(ah[mt], ra + OFF_AHI);
                ldsm_x4(al[mt], ra + OFF_ALO);
            }
            {
                uint32_t bh[4][4];
#pragma unroll
                for (int np = 0; np < 4; np++)
                    ldsm_x4(bh[np], st + OFF_BHI + (uint32_t)((rowB + np * 16) * ROWB) + boff);
#pragma unroll
                for (int mt = 0; mt < 2; mt++)
#pragma unroll
                    for (int np = 0; np < 4; np++) {
                        mma_bf16(d[mt][np * 2],     ah[mt], bh[np][0], bh[np][1]);
                        mma_bf16(d[mt][np * 2 + 1], ah[mt], bh[np][2], bh[np][3]);
                    }
#pragma unroll
                for (int mt = 0; mt < 2; mt++)
#pragma unroll
                    for (int np = 0; np < 4; np++) {
                        mma_bf16(d[mt][np * 2],     al[mt], bh[np][0], bh[np][1]);
                        mma_bf16(d[mt][np * 2 + 1], al[mt], bh[np][2], bh[np][3]);
                    }
            }
            {
                uint32_t bl[4][4];
#pragma unroll
                for (int np = 0; np < 4; np++)
                    ldsm_x4(bl[np], st + OFF_BLO + (uint32_t)((rowB + np * 16) * ROWB) + boff);
#pragma unroll
                for (int mt = 0; mt < 2; mt++)
#pragma unroll
                    for (int np = 0; np < 4; np++) {
                        mma_bf16(d[mt][np * 2],     ah[mt], bl[np][0], bl[np][1]);
                        mma_bf16(d[mt][np * 2 + 1], ah[mt], bl[np][2], bl[np][3]);
                    }
            }
        }
    }

#pragma unroll
    for (int mt = 0; mt < 2; mt++) {
#pragma unroll
        for (int np = 0; np < 4; np++) {
#pragma unroll
            for (int o = 0; o < 2; o++) {
                const float* dd = d[mt][np * 2 + o];
                int nb = n0 + warp_n + np * 16 + o * 8 + 2 * (L & 3);
                float bv0 = __ldg(bias + nb);
                float bv1 = __ldg(bias + nb + 1);
#pragma unroll
                for (int h = 0; h < 2; h++) {
                    int m = m0 + warp_m + mt * 16 + (L >> 2) + h * 8;
                    size_t obase = ((size_t)(m >> 12) << 20) + (size_t)(m & 4095);
                    outp[obase + ((size_t)nb << 12)] = dd[2 * h] + bv0;
                    outp[obase + ((size_t)(nb + 1) << 12)] = dd[2 * h + 1] + bv1;
                }
            }
        }
    }
}

// ---------------------------------------------------------------------------
extern "C" void kernel_launch(void* const* d_in, const int* in_sizes, int n_in,
                              void* d_out, int out_size) {
    const float* position = (const float*)d_in[0];
    const float* gestalt  = (const float*)d_in[1];
    const float* mask     = (const float*)d_in[2];
    const float* depth    = (const float*)d_in[3];
    const float* w1       = (const float*)d_in[4];
    const float* b1       = (const float*)d_in[5];
    const float* w2       = (const float*)d_in[6];
    const float* b2       = (const float*)d_in[7];
    float* out = (float*)d_out;
    (void)in_sizes; (void)n_in; (void)out_size;

    cudaFuncSetAttribute(gemm2_bf16x3, cudaFuncAttributeMaxDynamicSharedMemorySize, SMEM_DYN);
    cudaFuncSetAttribute(fused_h_kernel, cudaFuncAttributeMaxDynamicSharedMemorySize, FH_SMEM);

    __nv_bfloat16 *w2hi, *w2lo, *hhi, *hlo;
    cudaGetSymbolAddress((void**)&w2hi, g_W2hi);
    cudaGetSymbolAddress((void**)&w2lo, g_W2lo);
    cudaGetSymbolAddress((void**)&hhi, g_Hhi);
    cudaGetSymbolAddress((void**)&hlo, g_Hlo);

    cos_table_kernel<<<(2 * 16 * 16 * 128 + 255) / 256, 256>>>(position);
    u_kernel<<<dim3(4, 16), 256>>>(w1, gestalt);
    cxy_kernel<<<dim3(4, 4, 32), 256>>>(w1);
    split_w_kernel<<<(NOUT * HID + 255) / 256, 256>>>(w2, w2hi, w2lo, NOUT * HID);

    fused_h_kernel<<<dim3(32, 16), 256, FH_SMEM>>>(mask, depth, w1, b1);

    dim3 grid2(NOUT / BN, T_TOK / BM);  // (2, 512)
    gemm2_bf16x3<<<grid2, 256, SMEM_DYN>>>(hhi, hlo, w2hi, w2lo, HID, HID / BK, b2, out);
}

// round 6
// speedup vs baseline: 8.0013x; 1.0033x over previous
#include <cuda_runtime.h>
#include <cuda_bf16.h>
#include <math.h>
#include <stdint.h>

#define T_TOK 65536      // B * (H/2) * (W/2)
#define K_REAL 1156
#define HID 1024
#define NOUT 256

// ---------------- scratch (device globals; allocation-free) ----------------
__device__ __align__(16) __nv_bfloat16 g_Hhi[(size_t)T_TOK * HID];
__device__ __align__(16) __nv_bfloat16 g_Hlo[(size_t)T_TOK * HID];
__device__ __align__(16) __nv_bfloat16 g_W2hi[NOUT * HID];
__device__ __align__(16) __nv_bfloat16 g_W2lo[NOUT * HID];
__device__ __align__(16) float g_U[16 * 4 * HID];        // [b][s][n]
__device__ __align__(16) float g_CX[16 * 4 * 64 * HID];  // [b][s][j][n]
__device__ __align__(16) float g_CY[16 * 4 * 64 * HID];  // [b][s][i][n]

// ---------------- PTX helpers (baseline PTX only) ----------------
__device__ __forceinline__ uint32_t smem_u32(const void* p) {
    uint32_t a;
    asm("{ .reg .u64 t; cvta.to.shared.u64 t, %1; cvt.u32.u64 %0, t; }"
        : "=r"(a) : "l"(p));
    return a;
}
__device__ __forceinline__ void cp_async16(uint32_t dst, const void* src) {
    asm volatile("cp.async.cg.shared.global [%0], [%1], 16;"
                 :: "r"(dst), "l"(src));
}
#define CP_COMMIT() asm volatile("cp.async.commit_group;" ::: "memory")
#define CP_WAIT(n)  asm volatile("cp.async.wait_group %0;" :: "n"(n) : "memory")

__device__ __forceinline__ void ldsm_x4(uint32_t* r, uint32_t addr) {
    asm volatile("ldmatrix.sync.aligned.m8n8.x4.shared.b16 {%0,%1,%2,%3}, [%4];"
                 : "=r"(r[0]), "=r"(r[1]), "=r"(r[2]), "=r"(r[3]) : "r"(addr));
}
__device__ __forceinline__ void mma_bf16(float* d, const uint32_t* a,
                                         uint32_t b0, uint32_t b1) {
    asm volatile("mma.sync.aligned.m16n8k16.row.col.f32.bf16.bf16.f32 "
                 "{%0,%1,%2,%3}, {%4,%5,%6,%7}, {%8,%9}, {%0,%1,%2,%3};"
                 : "+f"(d[0]), "+f"(d[1]), "+f"(d[2]), "+f"(d[3])
                 : "r"(a[0]), "r"(a[1]), "r"(a[2]), "r"(a[3]), "r"(b0), "r"(b1));
}

// ---------------------------------------------------------------------------
// Launch 1: CX/CY kernel with inline cos table (bit-exact fp32 arg + double cos)
// CX[b][s][j][n] = sum_f W1[n, 1024 + 8f + s] * cos(ax=0, b, f, 2j+sx)
// CY[b][s][i][n] = sum_f W1[n, 1028 + 8f + s] * cos(ax=1, b, f, 2i+sy)
// grid (4 nquarters, 4 s, 32 b+ax), 256 threads.
// ---------------------------------------------------------------------------
__global__ void cxy_kernel(const float* __restrict__ w1,
                           const float* __restrict__ pos) {
    __shared__ float scos[1024];   // [f][j] for this (ax, b, sub)
    int n = blockIdx.x * 256 + threadIdx.x;
    int s = blockIdx.y;
    int bz = blockIdx.z;
    int b = bz & 15;
    int ax = bz >> 4;
    int sub = ax ? (s >> 1) : (s & 1);   // sy for y-axis, sx for x-axis

    // compute the 1024 needed cos values (f in [0,16), j in [0,64))
    {
        const float HALF_PI = 1.57079632679489661923f;
        float pw = pos[b * 4 + 3];
        float stdv = __fdiv_rn(0.1f, fminf(fmaxf(pw, 0.0078125f), 0.5f));
        float ctr = fminf(fmaxf(pos[b * 4 + (ax ? 1 : 0)], -1.f), 1.f);
#pragma unroll
        for (int k = 0; k < 4; k++) {
            int idx = threadIdx.x + k * 256;
            int f = idx >> 6;
            int j = idx & 63;
            int w = 2 * j + sub;
            float g = __fsub_rn(__fmul_rn(__fdiv_rn((float)w, 127.0f), 2.0f), 1.0f);
            float fs = (float)(1 << f);
            float a = __fmul_rn(__fmul_rn(__fmul_rn(__fsub_rn(g, ctr), stdv), HALF_PI), fs);
            scos[idx] = (float)cos((double)a);
        }
    }
    __syncthreads();

    float w[16];
    size_t base = (size_t)n * K_REAL + 1024 + (ax ? 4 : 0) + s;
#pragma unroll
    for (int f = 0; f < 16; f++) w[f] = w1[base + 8 * f];
    float* outp = (ax ? g_CY : g_CX) + ((size_t)(b * 4 + s) * 64) * HID + n;
#pragma unroll 2
    for (int j = 0; j < 64; j++) {
        float acc = 0.f;
#pragma unroll
        for (int f = 0; f < 16; f++) acc += w[f] * scos[f * 64 + j];
        outp[(size_t)j * HID] = acc;
    }
}

// ---------------------------------------------------------------------------
// Launch 2: misc kernel = U fold (blocks 0..63) + W2 hi/lo split (blocks 64..)
// ---------------------------------------------------------------------------
__global__ void misc_kernel(const float* __restrict__ w1,
                            const float* __restrict__ gestalt,
                            const float* __restrict__ w2) {
    int bx = blockIdx.x;
    if (bx < 64) {
        // U[b][s][n] = sum_c W1[n, 4c+s] * gestalt[b, c]
        int n = (bx & 3) * 256 + threadIdx.x;
        int b = bx >> 2;
        const float4* wrow = (const float4*)(w1 + (size_t)n * K_REAL);
        const float* g = gestalt + b * 256;
        float a0 = 0.f, a1 = 0.f, a2 = 0.f, a3 = 0.f;
#pragma unroll 4
        for (int c = 0; c < 256; c++) {
            float4 w = wrow[c];
            float gv = g[c];
            a0 += w.x * gv; a1 += w.y * gv; a2 += w.z * gv; a3 += w.w * gv;
        }
        g_U[(b * 4 + 0) * HID + n] = a0;
        g_U[(b * 4 + 1) * HID + n] = a1;
        g_U[(b * 4 + 2) * HID + n] = a2;
        g_U[(b * 4 + 3) * HID + n] = a3;
    } else {
        int idx = (bx - 64) * 256 + threadIdx.x;
        if (idx < NOUT * HID) {
            float v = w2[idx];
            __nv_bfloat16 h = __float2bfloat16(v);
            g_W2hi[idx] = h;
            g_W2lo[idx] = __float2bfloat16(v - __bfloat162float(h));
        }
    }
}

// ---------------------------------------------------------------------------
// Launch 3: Fused H: h[t,n] = b1[n] + sum_s m_s * (U + CX[j] + CY[i] + d_s*Wd);
// fast SiLU; split to bf16 hi/lo -> g_Hhi/g_Hlo (streaming stores).
// ---------------------------------------------------------------------------
#define FH_SMEM (16672 * 4)

__global__ __launch_bounds__(256) void fused_h_kernel(
    const float* __restrict__ mask, const float* __restrict__ depth,
    const float* __restrict__ w1, const float* __restrict__ b1) {
    extern __shared__ float sm[];
    float* sCX = sm;             // [s][j][nl]  4*64*32
    float* sCY = sm + 8192;      // [s][i][nl]
    float* sU  = sm + 16384;     // [s][nl]
    float* sWd = sm + 16512;     // [s][nl]
    float* sB  = sm + 16640;     // [nl]

    const int b  = blockIdx.y;
    const int n0 = blockIdx.x * 32;
    const int tid = threadIdx.x;

    for (int idx = tid; idx < 8192; idx += 256) {
        int nl = idx & 31, j = (idx >> 5) & 63, s = idx >> 11;
        size_t go = ((size_t)(b * 4 + s) * 64 + j) * HID + n0 + nl;
        sCX[idx] = g_CX[go];
        sCY[idx] = g_CY[go];
    }
    if (tid < 128) {
        int s = tid >> 5, nl = tid & 31;
        sU[tid]  = g_U[(b * 4 + s) * HID + n0 + nl];
        sWd[tid] = w1[(size_t)(n0 + nl) * K_REAL + 1152 + s];
    }
    if (tid < 32) sB[tid] = b1[n0 + tid];
    __syncthreads();

    const int npl = (tid & 15) * 2;
    const int tg  = tid >> 4;

    float2 u[4], wd[4], bb;
#pragma unroll
    for (int s = 0; s < 4; s++) {
        u[s]  = *(float2*)&sU[s * 32 + npl];
        wd[s] = *(float2*)&sWd[s * 32 + npl];
    }
    bb = *(float2*)&sB[npl];

#pragma unroll 1
    for (int ib = 0; ib < 4; ib++) {
        int i = tg * 4 + ib;
        float2 uc[4];
#pragma unroll
        for (int s = 0; s < 4; s++) {
            float2 cy = *(float2*)&sCY[s * 2048 + i * 32 + npl];
            uc[s].x = u[s].x + cy.x;
            uc[s].y = u[s].y + cy.y;
        }
        const float* mrow = mask  + b * 16384 + i * 256;
        const float* drow = depth + b * 16384 + i * 256;
        size_t rowbase = ((size_t)(b * 4096 + i * 64)) * HID + n0 + npl;
#pragma unroll 2
        for (int j = 0; j < 64; j++) {
            float m00 = mrow[2 * j],       m01 = mrow[2 * j + 1];
            float m10 = mrow[2 * j + 128], m11 = mrow[2 * j + 129];
            float d00 = drow[2 * j],       d01 = drow[2 * j + 1];
            float d10 = drow[2 * j + 128], d11 = drow[2 * j + 129];
            float2 cx0 = *(float2*)&sCX[0 * 2048 + j * 32 + npl];
            float2 cx1 = *(float2*)&sCX[1 * 2048 + j * 32 + npl];
            float2 cx2 = *(float2*)&sCX[2 * 2048 + j * 32 + npl];
            float2 cx3 = *(float2*)&sCX[3 * 2048 + j * 32 + npl];

            union { __nv_bfloat16 h2[2]; uint32_t uu; } HP, LP;
#pragma unroll
            for (int q = 0; q < 2; q++) {
                float c0 = (q ? uc[0].y + cx0.y : uc[0].x + cx0.x);
                float c1 = (q ? uc[1].y + cx1.y : uc[1].x + cx1.x);
                float c2 = (q ? uc[2].y + cx2.y : uc[2].x + cx2.x);
                float c3 = (q ? uc[3].y + cx3.y : uc[3].x + cx3.x);
                float w0  = (q ? wd[0].y : wd[0].x);
                float w1v = (q ? wd[1].y : wd[1].x);
                float w2v = (q ? wd[2].y : wd[2].x);
                float w3  = (q ? wd[3].y : wd[3].x);
                float h = (q ? bb.y : bb.x);
                h += m00 * (c0 + d00 * w0);
                h += m01 * (c1 + d01 * w1v);
                h += m10 * (c2 + d10 * w2v);
                h += m11 * (c3 + d11 * w3);
                float v = h * __frcp_rn(1.0f + __expf(-h));
                __nv_bfloat16 hh = __float2bfloat16(v);
                HP.h2[q] = hh;
                LP.h2[q] = __float2bfloat16(v - __bfloat162float(hh));
            }
            size_t off = rowbase + (size_t)j * HID;
            __stcs((uint32_t*)(g_Hhi + off), HP.uu);
            __stcs((uint32_t*)(g_Hlo + off), LP.uu);
        }
    }
}

// ---------------------------------------------------------------------------
// Launch 4 (ncu-captured slot): bf16x3 GEMM via mma.sync.
// C = A * B^T, +bias, scatter out. CTA 128x128, BK=32, 8 warps (4Mx2N).
// ---------------------------------------------------------------------------
#define BM 128
#define BN 128
#define BK 32
#define ROWB 80
#define TILE_B (BM * ROWB)
#define OFF_AHI 0
#define OFF_ALO TILE_B
#define OFF_BHI (2 * TILE_B)
#define OFF_BLO (3 * TILE_B)
#define STAGE_B (4 * TILE_B)
#define SMEM_DYN (2 * STAGE_B)

__device__ __forceinline__ void cp_chunk(uint32_t st,
                                         const __nv_bfloat16* Ah, const __nv_bfloat16* Al,
                                         const __nv_bfloat16* Bh, const __nv_bfloat16* Bl,
                                         int K, int k0, int tid) {
#pragma unroll
    for (int it = 0; it < 2; it++) {
        int idx = tid + it * 256;
        int r = idx >> 2, q = idx & 3;
        uint32_t o = (uint32_t)(r * ROWB + q * 16);
        size_t so = (size_t)r * K + k0 + q * 8;
        cp_async16(st + OFF_AHI + o, Ah + so);
        cp_async16(st + OFF_ALO + o, Al + so);
        cp_async16(st + OFF_BHI + o, Bh + so);
        cp_async16(st + OFF_BLO + o, Bl + so);
    }
}

__global__ __launch_bounds__(256, 2) void gemm2_bf16x3(
    const __nv_bfloat16* __restrict__ Ahi, const __nv_bfloat16* __restrict__ Alo,
    const __nv_bfloat16* __restrict__ Bhi, const __nv_bfloat16* __restrict__ Blo,
    int K, int NCH, const float* __restrict__ bias, float* __restrict__ outp) {
    extern __shared__ char dsm[];
    uint32_t sb = smem_u32(dsm);

    const int tid = threadIdx.x;
    const int wid = tid >> 5;
    const int L = tid & 31;
    const int m0 = blockIdx.y * BM;
    const int n0 = blockIdx.x * BN;
    const int warp_m = (wid >> 1) * 32;
    const int warp_n = (wid & 1) * 64;

    const __nv_bfloat16* Ah = Ahi + (size_t)m0 * K;
    const __nv_bfloat16* Al = Alo + (size_t)m0 * K;
    const __nv_bfloat16* Bh = Bhi + (size_t)n0 * K;
    const __nv_bfloat16* Bl = Blo + (size_t)n0 * K;

    const int rowA = warp_m + (L & 7) + ((L >> 3) & 1) * 8;
    const int colA = (L >> 4) * 8;
    const int rowB = warp_n + (L & 7) + (L >> 4) * 8;
    const int colB = ((L >> 3) & 1) * 8;

    float d[2][8][4];
#pragma unroll
    for (int i = 0; i < 2; i++)
#pragma unroll
        for (int j = 0; j < 8; j++)
#pragma unroll
            for (int e = 0; e < 4; e++) d[i][j][e] = 0.0f;

    cp_chunk(sb, Ah, Al, Bh, Bl, K, 0, tid);
    CP_COMMIT();

    for (int c = 0; c < NCH; c++) {
        CP_WAIT(0);
        __syncthreads();
        if (c + 1 < NCH) {
            cp_chunk(sb + ((c + 1) & 1) * STAGE_B, Ah, Al, Bh, Bl, K,
                     (c + 1) * BK, tid);
            CP_COMMIT();
        }
        uint32_t st = sb + (c & 1) * STAGE_B;
#pragma unroll
        for (int ks = 0; ks < 2; ks++) {
            uint32_t aoff = (uint32_t)((ks * 16 + colA) * 2);
            uint32_t boff = (uint32_t)((ks * 16 + colB) * 2);
            uint32_t ah[2][4], al[2][4];
#pragma unroll
            for (int mt = 0; mt < 2; mt++) {
                uint32_t ra = st + (uint32_t)((rowA + mt * 16) * ROWB) + aoff;
                ldsm_x4(ah[mt], ra + OFF_AHI);
                ldsm_x4(al[mt], ra + OFF_ALO);
            }
            {
                uint32_t bh[4][4];
#pragma unroll
                for (int np = 0; np < 4; np++)
                    ldsm_x4(bh[np], st + OFF_BHI + (uint32_t)((rowB + np * 16) * ROWB) + boff);
#pragma unroll
                for (int mt = 0; mt < 2; mt++)
#pragma unroll
                    for (int np = 0; np < 4; np++) {
                        mma_bf16(d[mt][np * 2],     ah[mt], bh[np][0], bh[np][1]);
                        mma_bf16(d[mt][np * 2 + 1], ah[mt], bh[np][2], bh[np][3]);
                    }
#pragma unroll
                for (int mt = 0; mt < 2; mt++)
#pragma unroll
                    for (int np = 0; np < 4; np++) {
                        mma_bf16(d[mt][np * 2],     al[mt], bh[np][0], bh[np][1]);
                        mma_bf16(d[mt][np * 2 + 1], al[mt], bh[np][2], bh[np][3]);
                    }
            }
            {
                uint32_t bl[4][4];
#pragma unroll
                for (int np = 0; np < 4; np++)
                    ldsm_x4(bl[np], st + OFF_BLO + (uint32_t)((rowB + np * 16) * ROWB) + boff);
#pragma unroll
                for (int mt = 0; mt < 2; mt++)
#pragma unroll
                    for (int np = 0; np < 4; np++) {
                        mma_bf16(d[mt][np * 2],     ah[mt], bl[np][0], bl[np][1]);
                        mma_bf16(d[mt][np * 2 + 1], ah[mt], bl[np][2], bl[np][3]);
                    }
            }
        }
    }

#pragma unroll
    for (int mt = 0; mt < 2; mt++) {
#pragma unroll
        for (int np = 0; np < 4; np++) {
#pragma unroll
            for (int o = 0; o < 2; o++) {
                const float* dd = d[mt][np * 2 + o];
                int nb = n0 + warp_n + np * 16 + o * 8 + 2 * (L & 3);
                float bv0 = __ldg(bias + nb);
                float bv1 = __ldg(bias + nb + 1);
#pragma unroll
                for (int h = 0; h < 2; h++) {
                    int m = m0 + warp_m + mt * 16 + (L >> 2) + h * 8;
                    size_t obase = ((size_t)(m >> 12) << 20) + (size_t)(m & 4095);
                    __stcs(outp + obase + ((size_t)nb << 12), dd[2 * h] + bv0);
                    __stcs(outp + obase + ((size_t)(nb + 1) << 12), dd[2 * h + 1] + bv1);
                }
            }
        }
    }
}

// ---------------------------------------------------------------------------
extern "C" void kernel_launch(void* const* d_in, const int* in_sizes, int n_in,
                              void* d_out, int out_size) {
    const float* position = (const float*)d_in[0];
    const float* gestalt  = (const float*)d_in[1];
    const float* mask     = (const float*)d_in[2];
    const float* depth    = (const float*)d_in[3];
    const float* w1       = (const float*)d_in[4];
    const float* b1       = (const float*)d_in[5];
    const float* w2       = (const float*)d_in[6];
    const float* b2       = (const float*)d_in[7];
    float* out = (float*)d_out;
    (void)in_sizes; (void)n_in; (void)out_size;

    cudaFuncSetAttribute(gemm2_bf16x3, cudaFuncAttributeMaxDynamicSharedMemorySize, SMEM_DYN);
    cudaFuncSetAttribute(fused_h_kernel, cudaFuncAttributeMaxDynamicSharedMemorySize, FH_SMEM);

    __nv_bfloat16 *w2hi, *w2lo, *hhi, *hlo;
    cudaGetSymbolAddress((void**)&w2hi, g_W2hi);
    cudaGetSymbolAddress((void**)&w2lo, g_W2lo);
    cudaGetSymbolAddress((void**)&hhi, g_Hhi);
    cudaGetSymbolAddress((void**)&hlo, g_Hlo);

    // Launch 1: CX/CY (inline cos)
    cxy_kernel<<<dim3(4, 4, 32), 256>>>(w1, position);
    // Launch 2: U fold + W2 split
    misc_kernel<<<64 + (NOUT * HID + 255) / 256, 256>>>(w1, gestalt, w2);
    // Launch 3: fused H
    fused_h_kernel<<<dim3(32, 16), 256, FH_SMEM>>>(mask, depth, w1, b1);
    // Launch 4: gemm2 (ncu capture slot)
    dim3 grid2(NOUT / BN, T_TOK / BM);  // (2, 512)
    gemm2_bf16x3<<<grid2, 256, SMEM_DYN>>>(hhi, hlo, w2hi, w2lo, HID, HID / BK, b2, out);
}

// round 7
// speedup vs baseline: 10.1237x; 1.2653x over previous
#include <cuda_runtime.h>
#include <cuda_fp16.h>
#include <math.h>
#include <stdint.h>

#define T_TOK 65536      // B * (H/2) * (W/2)
#define K_REAL 1156
#define HID 1024
#define NOUT 256

// ---------------- scratch (device globals; allocation-free) ----------------
__device__ __align__(16) __half g_Hhi[(size_t)T_TOK * HID];
__device__ __align__(16) __half g_Hlo[(size_t)T_TOK * HID];
__device__ __align__(16) __half g_W2h[NOUT * HID];
__device__ __align__(16) float g_U[16 * 4 * HID];        // [b][s][n]
__device__ __align__(16) float g_CX[16 * 4 * 64 * HID];  // [b][s][j][n]
__device__ __align__(16) float g_CY[16 * 4 * 64 * HID];  // [b][s][i][n]

// ---------------- PTX helpers (baseline PTX only) ----------------
__device__ __forceinline__ uint32_t smem_u32(const void* p) {
    uint32_t a;
    asm("{ .reg .u64 t; cvta.to.shared.u64 t, %1; cvt.u32.u64 %0, t; }"
        : "=r"(a) : "l"(p));
    return a;
}
__device__ __forceinline__ void cp_async16(uint32_t dst, const void* src) {
    asm volatile("cp.async.cg.shared.global [%0], [%1], 16;"
                 :: "r"(dst), "l"(src));
}
#define CP_COMMIT() asm volatile("cp.async.commit_group;" ::: "memory")
#define CP_WAIT(n)  asm volatile("cp.async.wait_group %0;" :: "n"(n) : "memory")

__device__ __forceinline__ void ldsm_x4(uint32_t* r, uint32_t addr) {
    asm volatile("ldmatrix.sync.aligned.m8n8.x4.shared.b16 {%0,%1,%2,%3}, [%4];"
                 : "=r"(r[0]), "=r"(r[1]), "=r"(r[2]), "=r"(r[3]) : "r"(addr));
}
__device__ __forceinline__ void mma_f16(float* d, const uint32_t* a,
                                        uint32_t b0, uint32_t b1) {
    asm volatile("mma.sync.aligned.m16n8k16.row.col.f32.f16.f16.f32 "
                 "{%0,%1,%2,%3}, {%4,%5,%6,%7}, {%8,%9}, {%0,%1,%2,%3};"
                 : "+f"(d[0]), "+f"(d[1]), "+f"(d[2]), "+f"(d[3])
                 : "r"(a[0]), "r"(a[1]), "r"(a[2]), "r"(a[3]), "r"(b0), "r"(b1));
}

// ---------------------------------------------------------------------------
// Launch 1: CX/CY with inline cos table (bit-exact fp32 arg chain + double cos)
// ---------------------------------------------------------------------------
__global__ void cxy_kernel(const float* __restrict__ w1,
                           const float* __restrict__ pos) {
    __shared__ float scos[1024];   // [f][j] for this (ax, b, sub)
    int n = blockIdx.x * 256 + threadIdx.x;
    int s = blockIdx.y;
    int bz = blockIdx.z;
    int b = bz & 15;
    int ax = bz >> 4;
    int sub = ax ? (s >> 1) : (s & 1);

    {
        const float HALF_PI = 1.57079632679489661923f;
        float pw = pos[b * 4 + 3];
        float stdv = __fdiv_rn(0.1f, fminf(fmaxf(pw, 0.0078125f), 0.5f));
        float ctr = fminf(fmaxf(pos[b * 4 + (ax ? 1 : 0)], -1.f), 1.f);
#pragma unroll
        for (int k = 0; k < 4; k++) {
            int idx = threadIdx.x + k * 256;
            int f = idx >> 6;
            int j = idx & 63;
            int w = 2 * j + sub;
            float g = __fsub_rn(__fmul_rn(__fdiv_rn((float)w, 127.0f), 2.0f), 1.0f);
            float fs = (float)(1 << f);
            float a = __fmul_rn(__fmul_rn(__fmul_rn(__fsub_rn(g, ctr), stdv), HALF_PI), fs);
            scos[idx] = (float)cos((double)a);
        }
    }
    __syncthreads();

    float w[16];
    size_t base = (size_t)n * K_REAL + 1024 + (ax ? 4 : 0) + s;
#pragma unroll
    for (int f = 0; f < 16; f++) w[f] = w1[base + 8 * f];
    float* outp = (ax ? g_CY : g_CX) + ((size_t)(b * 4 + s) * 64) * HID + n;
#pragma unroll 2
    for (int j = 0; j < 64; j++) {
        float acc = 0.f;
#pragma unroll
        for (int f = 0; f < 16; f++) acc += w[f] * scos[f * 64 + j];
        outp[(size_t)j * HID] = acc;
    }
}

// ---------------------------------------------------------------------------
// Launch 2: misc = U fold (blocks 0..63) + W2 fp16 convert (blocks 64..)
// ---------------------------------------------------------------------------
__global__ void misc_kernel(const float* __restrict__ w1,
                            const float* __restrict__ gestalt,
                            const float* __restrict__ w2) {
    int bx = blockIdx.x;
    if (bx < 64) {
        int n = (bx & 3) * 256 + threadIdx.x;
        int b = bx >> 2;
        const float4* wrow = (const float4*)(w1 + (size_t)n * K_REAL);
        const float* g = gestalt + b * 256;
        float a0 = 0.f, a1 = 0.f, a2 = 0.f, a3 = 0.f;
#pragma unroll 4
        for (int c = 0; c < 256; c++) {
            float4 w = wrow[c];
            float gv = g[c];
            a0 += w.x * gv; a1 += w.y * gv; a2 += w.z * gv; a3 += w.w * gv;
        }
        g_U[(b * 4 + 0) * HID + n] = a0;
        g_U[(b * 4 + 1) * HID + n] = a1;
        g_U[(b * 4 + 2) * HID + n] = a2;
        g_U[(b * 4 + 3) * HID + n] = a3;
    } else {
        int idx = (bx - 64) * 256 + threadIdx.x;
        if (idx < NOUT * HID) g_W2h[idx] = __float2half_rn(w2[idx]);
    }
}

// ---------------------------------------------------------------------------
// Launch 3: Fused H. h[t,n]=b1[n]+sum_s m_s*(U+CX[j]+CY[i]+d_s*Wd); SiLU;
// split to fp16 hi/lo. 4 n per thread, uint2 streaming stores.
// ---------------------------------------------------------------------------
#define FH_SMEM (16672 * 4)

__global__ __launch_bounds__(256) void fused_h_kernel(
    const float* __restrict__ mask, const float* __restrict__ depth,
    const float* __restrict__ w1, const float* __restrict__ b1) {
    extern __shared__ float sm[];
    float* sCX = sm;             // [s][j][nl]  4*64*32
    float* sCY = sm + 8192;      // [s][i][nl]
    float* sU  = sm + 16384;     // [s][nl]
    float* sWd = sm + 16512;     // [s][nl]
    float* sB  = sm + 16640;     // [nl]

    const int b  = blockIdx.y;
    const int n0 = blockIdx.x * 32;
    const int tid = threadIdx.x;

    for (int idx = tid; idx < 8192; idx += 256) {
        int nl = idx & 31, j = (idx >> 5) & 63, s = idx >> 11;
        size_t go = ((size_t)(b * 4 + s) * 64 + j) * HID + n0 + nl;
        sCX[idx] = g_CX[go];
        sCY[idx] = g_CY[go];
    }
    if (tid < 128) {
        int s = tid >> 5, nl = tid & 31;
        sU[tid]  = g_U[(b * 4 + s) * HID + n0 + nl];
        sWd[tid] = w1[(size_t)(n0 + nl) * K_REAL + 1152 + s];
    }
    if (tid < 32) sB[tid] = b1[n0 + tid];
    __syncthreads();

    const int npl = (tid & 7) * 4;    // 4 consecutive n
    const int tg  = tid >> 3;         // 32 i-groups

    float us[4][4], wds[4][4], bbs[4];
#pragma unroll
    for (int s = 0; s < 4; s++) {
        float4 tu = *(float4*)&sU[s * 32 + npl];
        us[s][0] = tu.x; us[s][1] = tu.y; us[s][2] = tu.z; us[s][3] = tu.w;
        float4 tw = *(float4*)&sWd[s * 32 + npl];
        wds[s][0] = tw.x; wds[s][1] = tw.y; wds[s][2] = tw.z; wds[s][3] = tw.w;
    }
    {
        float4 tb = *(float4*)&sB[npl];
        bbs[0] = tb.x; bbs[1] = tb.y; bbs[2] = tb.z; bbs[3] = tb.w;
    }

#pragma unroll 1
    for (int ib = 0; ib < 2; ib++) {
        int i = ib * 32 + tg;
        float uc[4][4];
#pragma unroll
        for (int s = 0; s < 4; s++) {
            float4 tc = *(float4*)&sCY[s * 2048 + i * 32 + npl];
            uc[s][0] = us[s][0] + tc.x;
            uc[s][1] = us[s][1] + tc.y;
            uc[s][2] = us[s][2] + tc.z;
            uc[s][3] = us[s][3] + tc.w;
        }
        const float* mrow = mask  + b * 16384 + i * 256;
        const float* drow = depth + b * 16384 + i * 256;
        size_t rowbase = ((size_t)(b * 4096 + i * 64)) * HID + n0 + npl;
#pragma unroll 2
        for (int j = 0; j < 64; j++) {
            float m00 = mrow[2 * j],       m01 = mrow[2 * j + 1];
            float m10 = mrow[2 * j + 128], m11 = mrow[2 * j + 129];
            float d00 = drow[2 * j],       d01 = drow[2 * j + 1];
            float d10 = drow[2 * j + 128], d11 = drow[2 * j + 129];
            float cxs[4][4];
#pragma unroll
            for (int s = 0; s < 4; s++) {
                float4 tc = *(float4*)&sCX[s * 2048 + j * 32 + npl];
                cxs[s][0] = tc.x; cxs[s][1] = tc.y; cxs[s][2] = tc.z; cxs[s][3] = tc.w;
            }
            union { __half h4[4]; uint2 u2; } HP, LP;
#pragma unroll
            for (int q = 0; q < 4; q++) {
                float h = bbs[q];
                h += m00 * (uc[0][q] + cxs[0][q] + d00 * wds[0][q]);
                h += m01 * (uc[1][q] + cxs[1][q] + d01 * wds[1][q]);
                h += m10 * (uc[2][q] + cxs[2][q] + d10 * wds[2][q]);
                h += m11 * (uc[3][q] + cxs[3][q] + d11 * wds[3][q]);
                float v = h * __frcp_rn(1.0f + __expf(-h));
                __half hh = __float2half_rn(v);
                HP.h4[q] = hh;
                LP.h4[q] = __float2half_rn(v - __half2float(hh));
            }
            size_t off = rowbase + (size_t)j * HID;
            __stcs((uint2*)(g_Hhi + off), HP.u2);
            __stcs((uint2*)(g_Hlo + off), LP.u2);
        }
    }
}

// ---------------------------------------------------------------------------
// Launch 4 (ncu slot): fp16x2 GEMM via mma.sync: C = (Ah+Al) * B^T.
// CTA 128x128, BK=32, 8 warps (4Mx2N). 3-stage cp.async pipeline.
// Stage = Ahi + Alo + Bh (30KB); 2 CTAs/SM.
// ---------------------------------------------------------------------------
#define BM 128
#define BN 128
#define BK 32
#define ROWB 80
#define TILE_B (BM * ROWB)      // 10240
#define OFF_AHI 0
#define OFF_ALO TILE_B
#define OFF_BH  (2 * TILE_B)
#define STAGE_B (3 * TILE_B)    // 30720
#define SMEM_DYN (3 * STAGE_B)  // 92160

__device__ __forceinline__ void cp_chunk(uint32_t st,
                                         const __half* Ah, const __half* Al,
                                         const __half* Bh,
                                         int K, int k0, int tid) {
#pragma unroll
    for (int it = 0; it < 2; it++) {
        int idx = tid + it * 256;
        int r = idx >> 2, q = idx & 3;
        uint32_t o = (uint32_t)(r * ROWB + q * 16);
        size_t so = (size_t)r * K + k0 + q * 8;
        cp_async16(st + OFF_AHI + o, Ah + so);
        cp_async16(st + OFF_ALO + o, Al + so);
        cp_async16(st + OFF_BH  + o, Bh + so);
    }
}

__global__ __launch_bounds__(256, 2) void gemm2_f16x2(
    const __half* __restrict__ Ahi, const __half* __restrict__ Alo,
    const __half* __restrict__ Bh_g,
    int K, int NCH, const float* __restrict__ bias, float* __restrict__ outp) {
    extern __shared__ char dsm[];
    uint32_t sb = smem_u32(dsm);

    const int tid = threadIdx.x;
    const int wid = tid >> 5;
    const int L = tid & 31;
    const int m0 = blockIdx.y * BM;
    const int n0 = blockIdx.x * BN;
    const int warp_m = (wid >> 1) * 32;
    const int warp_n = (wid & 1) * 64;

    const __half* Ah = Ahi + (size_t)m0 * K;
    const __half* Al = Alo + (size_t)m0 * K;
    const __half* Bh = Bh_g + (size_t)n0 * K;

    const int rowA = warp_m + (L & 7) + ((L >> 3) & 1) * 8;
    const int colA = (L >> 4) * 8;
    const int rowB = warp_n + (L & 7) + (L >> 4) * 8;
    const int colB = ((L >> 3) & 1) * 8;

    float d[2][8][4];
#pragma unroll
    for (int i = 0; i < 2; i++)
#pragma unroll
        for (int j = 0; j < 8; j++)
#pragma unroll
            for (int e = 0; e < 4; e++) d[i][j][e] = 0.0f;

    cp_chunk(sb + 0 * STAGE_B, Ah, Al, Bh, K, 0, tid);
    CP_COMMIT();
    cp_chunk(sb + 1 * STAGE_B, Ah, Al, Bh, K, BK, tid);
    CP_COMMIT();

    int stage = 0;
    for (int c = 0; c < NCH; c++) {
        if (c == NCH - 1) { CP_WAIT(0); } else { CP_WAIT(1); }
        __syncthreads();
        if (c + 2 < NCH) {
            int ps = stage + 2; if (ps >= 3) ps -= 3;
            cp_chunk(sb + ps * STAGE_B, Ah, Al, Bh, K, (c + 2) * BK, tid);
            CP_COMMIT();
        }
        uint32_t st = sb + stage * STAGE_B;
#pragma unroll
        for (int ks = 0; ks < 2; ks++) {
            uint32_t aoff = (uint32_t)((ks * 16 + colA) * 2);
            uint32_t boff = (uint32_t)((ks * 16 + colB) * 2);
            uint32_t ah[2][4], al[2][4], bh[4][4];
#pragma unroll
            for (int mt = 0; mt < 2; mt++) {
                uint32_t ra = st + (uint32_t)((rowA + mt * 16) * ROWB) + aoff;
                ldsm_x4(ah[mt], ra + OFF_AHI);
                ldsm_x4(al[mt], ra + OFF_ALO);
            }
#pragma unroll
            for (int np = 0; np < 4; np++)
                ldsm_x4(bh[np], st + OFF_BH + (uint32_t)((rowB + np * 16) * ROWB) + boff);
#pragma unroll
            for (int mt = 0; mt < 2; mt++)
#pragma unroll
                for (int np = 0; np < 4; np++) {
                    mma_f16(d[mt][np * 2],     ah[mt], bh[np][0], bh[np][1]);
                    mma_f16(d[mt][np * 2 + 1], ah[mt], bh[np][2], bh[np][3]);
                }
#pragma unroll
            for (int mt = 0; mt < 2; mt++)
#pragma unroll
                for (int np = 0; np < 4; np++) {
                    mma_f16(d[mt][np * 2],     al[mt], bh[np][0], bh[np][1]);
                    mma_f16(d[mt][np * 2 + 1], al[mt], bh[np][2], bh[np][3]);
                }
        }
        stage++; if (stage >= 3) stage = 0;
    }

#pragma unroll
    for (int mt = 0; mt < 2; mt++) {
#pragma unroll
        for (int np = 0; np < 4; np++) {
#pragma unroll
            for (int o = 0; o < 2; o++) {
                const float* dd = d[mt][np * 2 + o];
                int nb = n0 + warp_n + np * 16 + o * 8 + 2 * (L & 3);
                float bv0 = __ldg(bias + nb);
                float bv1 = __ldg(bias + nb + 1);
#pragma unroll
                for (int h = 0; h < 2; h++) {
                    int m = m0 + warp_m + mt * 16 + (L >> 2) + h * 8;
                    size_t obase = ((size_t)(m >> 12) << 20) + (size_t)(m & 4095);
                    __stcs(outp + obase + ((size_t)nb << 12), dd[2 * h] + bv0);
                    __stcs(outp + obase + ((size_t)(nb + 1) << 12), dd[2 * h + 1] + bv1);
                }
            }
        }
    }
}

// ---------------------------------------------------------------------------
extern "C" void kernel_launch(void* const* d_in, const int* in_sizes, int n_in,
                              void* d_out, int out_size) {
    const float* position = (const float*)d_in[0];
    const float* gestalt  = (const float*)d_in[1];
    const float* mask     = (const float*)d_in[2];
    const float* depth    = (const float*)d_in[3];
    const float* w1       = (const float*)d_in[4];
    const float* b1       = (const float*)d_in[5];
    const float* w2       = (const float*)d_in[6];
    const float* b2       = (const float*)d_in[7];
    float* out = (float*)d_out;
    (void)in_sizes; (void)n_in; (void)out_size;

    cudaFuncSetAttribute(gemm2_f16x2, cudaFuncAttributeMaxDynamicSharedMemorySize, SMEM_DYN);
    cudaFuncSetAttribute(fused_h_kernel, cudaFuncAttributeMaxDynamicSharedMemorySize, FH_SMEM);

    __half *w2h, *hhi, *hlo;
    cudaGetSymbolAddress((void**)&w2h, g_W2h);
    cudaGetSymbolAddress((void**)&hhi, g_Hhi);
    cudaGetSymbolAddress((void**)&hlo, g_Hlo);

    // Launch 1: CX/CY (inline cos)
    cxy_kernel<<<dim3(4, 4, 32), 256>>>(w1, position);
    // Launch 2: U fold + W2 fp16 convert
    misc_kernel<<<64 + (NOUT * HID + 255) / 256, 256>>>(w1, gestalt, w2);
    // Launch 3: fused H
    fused_h_kernel<<<dim3(32, 16), 256, FH_SMEM>>>(mask, depth, w1, b1);
    // Launch 4: gemm2 (ncu capture slot)
    dim3 grid2(NOUT / BN, T_TOK / BM);  // (2, 512)
    gemm2_f16x2<<<grid2, 256, SMEM_DYN>>>(hhi, hlo, w2h, HID, HID / BK, b2, out);
}

// round 8
// speedup vs baseline: 11.8942x; 1.1749x over previous
#include <cuda_runtime.h>
#include <cuda_fp16.h>
#include <math.h>
#include <stdint.h>

#define T_TOK 65536      // B * (H/2) * (W/2)
#define K_REAL 1156
#define HID 1024
#define NOUT 256

// ---------------- scratch (device globals; allocation-free) ----------------
__device__ __align__(16) __half g_Hh[(size_t)T_TOK * HID];
__device__ __align__(16) __half g_W2h[NOUT * HID];
__device__ __align__(16) float g_U[16 * 4 * HID];        // [b][s][n]
__device__ __align__(16) float g_CX[16 * 4 * 64 * HID];  // [b][s][j][n]
__device__ __align__(16) float g_CY[16 * 4 * 64 * HID];  // [b][s][i][n]

// ---------------- PTX helpers (baseline PTX only) ----------------
__device__ __forceinline__ uint32_t smem_u32(const void* p) {
    uint32_t a;
    asm("{ .reg .u64 t; cvta.to.shared.u64 t, %1; cvt.u32.u64 %0, t; }"
        : "=r"(a) : "l"(p));
    return a;
}
__device__ __forceinline__ void cp_async16(uint32_t dst, const void* src) {
    asm volatile("cp.async.cg.shared.global [%0], [%1], 16;"
                 :: "r"(dst), "l"(src));
}
#define CP_COMMIT() asm volatile("cp.async.commit_group;" ::: "memory")
#define CP_WAIT(n)  asm volatile("cp.async.wait_group %0;" :: "n"(n) : "memory")

__device__ __forceinline__ void ldsm_x4(uint32_t* r, uint32_t addr) {
    asm volatile("ldmatrix.sync.aligned.m8n8.x4.shared.b16 {%0,%1,%2,%3}, [%4];"
                 : "=r"(r[0]), "=r"(r[1]), "=r"(r[2]), "=r"(r[3]) : "r"(addr));
}
__device__ __forceinline__ void mma_f16(float* d, const uint32_t* a,
                                        uint32_t b0, uint32_t b1) {
    asm volatile("mma.sync.aligned.m16n8k16.row.col.f32.f16.f16.f32 "
                 "{%0,%1,%2,%3}, {%4,%5,%6,%7}, {%8,%9}, {%0,%1,%2,%3};"
                 : "+f"(d[0]), "+f"(d[1]), "+f"(d[2]), "+f"(d[3])
                 : "r"(a[0]), "r"(a[1]), "r"(a[2]), "r"(a[3]), "r"(b0), "r"(b1));
}

// ---------------------------------------------------------------------------
// Launch 1: CX/CY with inline cos table (bit-exact fp32 arg chain + double cos)
// ---------------------------------------------------------------------------
__global__ void cxy_kernel(const float* __restrict__ w1,
                           const float* __restrict__ pos) {
    __shared__ float scos[1024];   // [f][j] for this (ax, b, sub)
    int n = blockIdx.x * 256 + threadIdx.x;
    int s = blockIdx.y;
    int bz = blockIdx.z;
    int b = bz & 15;
    int ax = bz >> 4;
    int sub = ax ? (s >> 1) : (s & 1);

    {
        const float HALF_PI = 1.57079632679489661923f;
        float pw = pos[b * 4 + 3];
        float stdv = __fdiv_rn(0.1f, fminf(fmaxf(pw, 0.0078125f), 0.5f));
        float ctr = fminf(fmaxf(pos[b * 4 + (ax ? 1 : 0)], -1.f), 1.f);
#pragma unroll
        for (int k = 0; k < 4; k++) {
            int idx = threadIdx.x + k * 256;
            int f = idx >> 6;
            int j = idx & 63;
            int w = 2 * j + sub;
            float g = __fsub_rn(__fmul_rn(__fdiv_rn((float)w, 127.0f), 2.0f), 1.0f);
            float fs = (float)(1 << f);
            float a = __fmul_rn(__fmul_rn(__fmul_rn(__fsub_rn(g, ctr), stdv), HALF_PI), fs);
            scos[idx] = (float)cos((double)a);
        }
    }
    __syncthreads();

    float w[16];
    size_t base = (size_t)n * K_REAL + 1024 + (ax ? 4 : 0) + s;
#pragma unroll
    for (int f = 0; f < 16; f++) w[f] = w1[base + 8 * f];
    float* outp = (ax ? g_CY : g_CX) + ((size_t)(b * 4 + s) * 64) * HID + n;
#pragma unroll 2
    for (int j = 0; j < 64; j++) {
        float acc = 0.f;
#pragma unroll
        for (int f = 0; f < 16; f++) acc += w[f] * scos[f * 64 + j];
        outp[(size_t)j * HID] = acc;
    }
}

// ---------------------------------------------------------------------------
// Launch 2: misc = U fold (blocks 0..63) + W2 fp16 convert (blocks 64..)
// ---------------------------------------------------------------------------
__global__ void misc_kernel(const float* __restrict__ w1,
                            const float* __restrict__ gestalt,
                            const float* __restrict__ w2) {
    int bx = blockIdx.x;
    if (bx < 64) {
        int n = (bx & 3) * 256 + threadIdx.x;
        int b = bx >> 2;
        const float4* wrow = (const float4*)(w1 + (size_t)n * K_REAL);
        const float* g = gestalt + b * 256;
        float a0 = 0.f, a1 = 0.f, a2 = 0.f, a3 = 0.f;
#pragma unroll 4
        for (int c = 0; c < 256; c++) {
            float4 w = wrow[c];
            float gv = g[c];
            a0 += w.x * gv; a1 += w.y * gv; a2 += w.z * gv; a3 += w.w * gv;
        }
        g_U[(b * 4 + 0) * HID + n] = a0;
        g_U[(b * 4 + 1) * HID + n] = a1;
        g_U[(b * 4 + 2) * HID + n] = a2;
        g_U[(b * 4 + 3) * HID + n] = a3;
    } else {
        int idx = (bx - 64) * 256 + threadIdx.x;
        if (idx < NOUT * HID) g_W2h[idx] = __float2half_rn(w2[idx]);
    }
}

// ---------------------------------------------------------------------------
// Launch 3: Fused H. h[t,n]=b1[n]+sum_s m_s*(U+CX[j]+CY[i]+d_s*Wd); SiLU;
// single fp16 output. 4 n per thread, uint2 streaming stores.
// ---------------------------------------------------------------------------
#define FH_SMEM (16672 * 4)

__global__ __launch_bounds__(256) void fused_h_kernel(
    const float* __restrict__ mask, const float* __restrict__ depth,
    const float* __restrict__ w1, const float* __restrict__ b1) {
    extern __shared__ float sm[];
    float* sCX = sm;             // [s][j][nl]  4*64*32
    float* sCY = sm + 8192;      // [s][i][nl]
    float* sU  = sm + 16384;     // [s][nl]
    float* sWd = sm + 16512;     // [s][nl]
    float* sB  = sm + 16640;     // [nl]

    const int b  = blockIdx.y;
    const int n0 = blockIdx.x * 32;
    const int tid = threadIdx.x;

    for (int idx = tid; idx < 8192; idx += 256) {
        int nl = idx & 31, j = (idx >> 5) & 63, s = idx >> 11;
        size_t go = ((size_t)(b * 4 + s) * 64 + j) * HID + n0 + nl;
        sCX[idx] = g_CX[go];
        sCY[idx] = g_CY[go];
    }
    if (tid < 128) {
        int s = tid >> 5, nl = tid & 31;
        sU[tid]  = g_U[(b * 4 + s) * HID + n0 + nl];
        sWd[tid] = w1[(size_t)(n0 + nl) * K_REAL + 1152 + s];
    }
    if (tid < 32) sB[tid] = b1[n0 + tid];
    __syncthreads();

    const int npl = (tid & 7) * 4;    // 4 consecutive n
    const int tg  = tid >> 3;         // 32 i-groups

    float us[4][4], wds[4][4], bbs[4];
#pragma unroll
    for (int s = 0; s < 4; s++) {
        float4 tu = *(float4*)&sU[s * 32 + npl];
        us[s][0] = tu.x; us[s][1] = tu.y; us[s][2] = tu.z; us[s][3] = tu.w;
        float4 tw = *(float4*)&sWd[s * 32 + npl];
        wds[s][0] = tw.x; wds[s][1] = tw.y; wds[s][2] = tw.z; wds[s][3] = tw.w;
    }
    {
        float4 tb = *(float4*)&sB[npl];
        bbs[0] = tb.x; bbs[1] = tb.y; bbs[2] = tb.z; bbs[3] = tb.w;
    }

#pragma unroll 1
    for (int ib = 0; ib < 2; ib++) {
        int i = ib * 32 + tg;
        float uc[4][4];
#pragma unroll
        for (int s = 0; s < 4; s++) {
            float4 tc = *(float4*)&sCY[s * 2048 + i * 32 + npl];
            uc[s][0] = us[s][0] + tc.x;
            uc[s][1] = us[s][1] + tc.y;
            uc[s][2] = us[s][2] + tc.z;
            uc[s][3] = us[s][3] + tc.w;
        }
        const float* mrow = mask  + b * 16384 + i * 256;
        const float* drow = depth + b * 16384 + i * 256;
        size_t rowbase = ((size_t)(b * 4096 + i * 64)) * HID + n0 + npl;
#pragma unroll 2
        for (int j = 0; j < 64; j++) {
            float m00 = mrow[2 * j],       m01 = mrow[2 * j + 1];
            float m10 = mrow[2 * j + 128], m11 = mrow[2 * j + 129];
            float d00 = drow[2 * j],       d01 = drow[2 * j + 1];
            float d10 = drow[2 * j + 128], d11 = drow[2 * j + 129];
            union { __half h4[4]; uint2 u2; } HP;
#pragma unroll
            for (int q = 0; q < 4; q++) {
                float cx0 = sCX[0 * 2048 + j * 32 + npl + q];
                float cx1 = sCX[1 * 2048 + j * 32 + npl + q];
                float cx2 = sCX[2 * 2048 + j * 32 + npl + q];
                float cx3 = sCX[3 * 2048 + j * 32 + npl + q];
                float h = bbs[q];
                h += m00 * (uc[0][q] + cx0 + d00 * wds[0][q]);
                h += m01 * (uc[1][q] + cx1 + d01 * wds[1][q]);
                h += m10 * (uc[2][q] + cx2 + d10 * wds[2][q]);
                h += m11 * (uc[3][q] + cx3 + d11 * wds[3][q]);
                float v = __fdividef(h, 1.0f + __expf(-h));
                HP.h4[q] = __float2half_rn(v);
            }
            __stcs((uint2*)(g_Hh + rowbase + (size_t)j * HID), HP.u2);
        }
    }
}

// ---------------------------------------------------------------------------
// Launch 4 (ncu slot): single-pass fp16 GEMM via mma.sync: C = A * B^T.
// CTA 128x128, BK=32, 8 warps (4Mx2N). 4-stage cp.async pipeline, 2 CTAs/SM.
// ---------------------------------------------------------------------------
#define BM 128
#define BN 128
#define BK 32
#define ROWB 80
#define TILE_B (BM * ROWB)      // 10240
#define OFF_A 0
#define OFF_B TILE_B
#define STAGE_B (2 * TILE_B)    // 20480
#define NSTAGE 4
#define SMEM_DYN (NSTAGE * STAGE_B)  // 81920

__device__ __forceinline__ void cp_chunk(uint32_t st,
                                         const __half* A, const __half* B,
                                         int K, int k0, int tid) {
#pragma unroll
    for (int it = 0; it < 2; it++) {
        int idx = tid + it * 256;
        int r = idx >> 2, q = idx & 3;
        uint32_t o = (uint32_t)(r * ROWB + q * 16);
        size_t so = (size_t)r * K + k0 + q * 8;
        cp_async16(st + OFF_A + o, A + so);
        cp_async16(st + OFF_B + o, B + so);
    }
}

__global__ __launch_bounds__(256, 2) void gemm2_f16(
    const __half* __restrict__ A_g, const __half* __restrict__ B_g,
    int K, int NCH, const float* __restrict__ bias, float* __restrict__ outp) {
    extern __shared__ char dsm[];
    uint32_t sb = smem_u32(dsm);

    const int tid = threadIdx.x;
    const int wid = tid >> 5;
    const int L = tid & 31;
    const int m0 = blockIdx.y * BM;
    const int n0 = blockIdx.x * BN;
    const int warp_m = (wid >> 1) * 32;
    const int warp_n = (wid & 1) * 64;

    const __half* A = A_g + (size_t)m0 * K;
    const __half* B = B_g + (size_t)n0 * K;

    const int rowA = warp_m + (L & 7) + ((L >> 3) & 1) * 8;
    const int colA = (L >> 4) * 8;
    const int rowB = warp_n + (L & 7) + (L >> 4) * 8;
    const int colB = ((L >> 3) & 1) * 8;

    float d[2][8][4];
#pragma unroll
    for (int i = 0; i < 2; i++)
#pragma unroll
        for (int j = 0; j < 8; j++)
#pragma unroll
            for (int e = 0; e < 4; e++) d[i][j][e] = 0.0f;

    // prefetch stages 0..2
#pragma unroll
    for (int p = 0; p < NSTAGE - 1; p++) {
        cp_chunk(sb + p * STAGE_B, A, B, K, p * BK, tid);
        CP_COMMIT();
    }

    int stage = 0;
    for (int c = 0; c < NCH; c++) {
        if (c + NSTAGE - 1 < NCH) {
            int ps = stage + NSTAGE - 1; if (ps >= NSTAGE) ps -= NSTAGE;
            cp_chunk(sb + ps * STAGE_B, A, B, K, (c + NSTAGE - 1) * BK, tid);
            CP_COMMIT();
        }
        // ensure chunk c complete (exact tail handling)
        int rem = NCH - 1 - c;
        if (rem >= 3) { CP_WAIT(3); }
        else if (rem == 2) { CP_WAIT(2); }
        else if (rem == 1) { CP_WAIT(1); }
        else { CP_WAIT(0); }
        __syncthreads();

        uint32_t st = sb + stage * STAGE_B;
#pragma unroll
        for (int ks = 0; ks < 2; ks++) {
            uint32_t aoff = (uint32_t)((ks * 16 + colA) * 2);
            uint32_t boff = (uint32_t)((ks * 16 + colB) * 2);
            uint32_t ah[2][4], bh[4][4];
#pragma unroll
            for (int mt = 0; mt < 2; mt++)
                ldsm_x4(ah[mt], st + OFF_A + (uint32_t)((rowA + mt * 16) * ROWB) + aoff);
#pragma unroll
            for (int np = 0; np < 4; np++)
                ldsm_x4(bh[np], st + OFF_B + (uint32_t)((rowB + np * 16) * ROWB) + boff);
#pragma unroll
            for (int mt = 0; mt < 2; mt++)
#pragma unroll
                for (int np = 0; np < 4; np++) {
                    mma_f16(d[mt][np * 2],     ah[mt], bh[np][0], bh[np][1]);
                    mma_f16(d[mt][np * 2 + 1], ah[mt], bh[np][2], bh[np][3]);
                }
        }
        __syncthreads();
        stage++; if (stage >= NSTAGE) stage = 0;
    }

#pragma unroll
    for (int mt = 0; mt < 2; mt++) {
#pragma unroll
        for (int np = 0; np < 4; np++) {
#pragma unroll
            for (int o = 0; o < 2; o++) {
                const float* dd = d[mt][np * 2 + o];
                int nb = n0 + warp_n + np * 16 + o * 8 + 2 * (L & 3);
                float bv0 = __ldg(bias + nb);
                float bv1 = __ldg(bias + nb + 1);
#pragma unroll
                for (int h = 0; h < 2; h++) {
                    int m = m0 + warp_m + mt * 16 + (L >> 2) + h * 8;
                    size_t obase = ((size_t)(m >> 12) << 20) + (size_t)(m & 4095);
                    __stcs(outp + obase + ((size_t)nb << 12), dd[2 * h] + bv0);
                    __stcs(outp + obase + ((size_t)(nb + 1) << 12), dd[2 * h + 1] + bv1);
                }
            }
        }
    }
}

// ---------------------------------------------------------------------------
extern "C" void kernel_launch(void* const* d_in, const int* in_sizes, int n_in,
                              void* d_out, int out_size) {
    const float* position = (const float*)d_in[0];
    const float* gestalt  = (const float*)d_in[1];
    const float* mask     = (const float*)d_in[2];
    const float* depth    = (const float*)d_in[3];
    const float* w1       = (const float*)d_in[4];
    const float* b1       = (const float*)d_in[5];
    const float* w2       = (const float*)d_in[6];
    const float* b2       = (const float*)d_in[7];
    float* out = (float*)d_out;
    (void)in_sizes; (void)n_in; (void)out_size;

    cudaFuncSetAttribute(gemm2_f16, cudaFuncAttributeMaxDynamicSharedMemorySize, SMEM_DYN);
    cudaFuncSetAttribute(fused_h_kernel, cudaFuncAttributeMaxDynamicSharedMemorySize, FH_SMEM);

    __half *w2h, *hh;
    cudaGetSymbolAddress((void**)&w2h, g_W2h);
    cudaGetSymbolAddress((void**)&hh, g_Hh);

    // Launch 1: CX/CY (inline cos)
    cxy_kernel<<<dim3(4, 4, 32), 256>>>(w1, position);
    // Launch 2: U fold + W2 fp16 convert
    misc_kernel<<<64 + (NOUT * HID + 255) / 256, 256>>>(w1, gestalt, w2);
    // Launch 3: fused H
    fused_h_kernel<<<dim3(32, 16), 256, FH_SMEM>>>(mask, depth, w1, b1);
    // Launch 4: gemm2 (ncu capture slot)
    dim3 grid2(NOUT / BN, T_TOK / BM);  // (2, 512)
    gemm2_f16<<<grid2, 256, SMEM_DYN>>>(hh, w2h, HID, HID / BK, b2, out);
}

// round 9
// speedup vs baseline: 12.1787x; 1.0239x over previous
#include <cuda_runtime.h>
#include <cuda_fp16.h>
#include <math.h>
#include <stdint.h>

#define T_TOK 65536      // B * (H/2) * (W/2)
#define K_REAL 1156
#define HID 1024
#define NOUT 256

// ---------------- scratch (device globals; allocation-free) ----------------
__device__ __align__(16) __half g_Hh[(size_t)T_TOK * HID];
__device__ __align__(16) __half g_W2h[NOUT * HID];
__device__ __align__(16) float g_U[16 * 4 * HID];        // [b][s][n]
__device__ __align__(16) float g_CX[16 * 4 * 64 * HID];  // [b][s][j][n]
__device__ __align__(16) float g_CY[16 * 4 * 64 * HID];  // [b][s][i][n]

// ---------------- PTX helpers (baseline PTX only) ----------------
__device__ __forceinline__ uint32_t smem_u32(const void* p) {
    uint32_t a;
    asm("{ .reg .u64 t; cvta.to.shared.u64 t, %1; cvt.u32.u64 %0, t; }"
        : "=r"(a) : "l"(p));
    return a;
}
__device__ __forceinline__ void cp_async16(uint32_t dst, const void* src) {
    asm volatile("cp.async.cg.shared.global [%0], [%1], 16;"
                 :: "r"(dst), "l"(src));
}
#define CP_COMMIT() asm volatile("cp.async.commit_group;" ::: "memory")
#define CP_WAIT(n)  asm volatile("cp.async.wait_group %0;" :: "n"(n) : "memory")

__device__ __forceinline__ void ldsm_x4(uint32_t* r, uint32_t addr) {
    asm volatile("ldmatrix.sync.aligned.m8n8.x4.shared.b16 {%0,%1,%2,%3}, [%4];"
                 : "=r"(r[0]), "=r"(r[1]), "=r"(r[2]), "=r"(r[3]) : "r"(addr));
}
__device__ __forceinline__ void mma_f16(float* d, const uint32_t* a,
                                        uint32_t b0, uint32_t b1) {
    asm volatile("mma.sync.aligned.m16n8k16.row.col.f32.f16.f16.f32 "
                 "{%0,%1,%2,%3}, {%4,%5,%6,%7}, {%8,%9}, {%0,%1,%2,%3};"
                 : "+f"(d[0]), "+f"(d[1]), "+f"(d[2]), "+f"(d[3])
                 : "r"(a[0]), "r"(a[1]), "r"(a[2]), "r"(a[3]), "r"(b0), "r"(b1));
}

// ---------------------------------------------------------------------------
// Launch 1: W2 fp16 convert
// ---------------------------------------------------------------------------
__global__ void w2conv_kernel(const float* __restrict__ w2) {
    int idx = blockIdx.x * 256 + threadIdx.x;
    if (idx < NOUT * HID) g_W2h[idx] = __float2half_rn(w2[idx]);
}

// ---------------------------------------------------------------------------
// Launch 2: CX/CY with inline cos table (bit-exact fp32 arg chain + double cos)
// ---------------------------------------------------------------------------
__global__ void cxy_kernel(const float* __restrict__ w1,
                           const float* __restrict__ pos) {
    __shared__ float scos[1024];   // [f][j] for this (ax, b, sub)
    int n = blockIdx.x * 256 + threadIdx.x;
    int s = blockIdx.y;
    int bz = blockIdx.z;
    int b = bz & 15;
    int ax = bz >> 4;
    int sub = ax ? (s >> 1) : (s & 1);

    {
        const float HALF_PI = 1.57079632679489661923f;
        float pw = pos[b * 4 + 3];
        float stdv = __fdiv_rn(0.1f, fminf(fmaxf(pw, 0.0078125f), 0.5f));
        float ctr = fminf(fmaxf(pos[b * 4 + (ax ? 1 : 0)], -1.f), 1.f);
#pragma unroll
        for (int k = 0; k < 4; k++) {
            int idx = threadIdx.x + k * 256;
            int f = idx >> 6;
            int j = idx & 63;
            int w = 2 * j + sub;
            float g = __fsub_rn(__fmul_rn(__fdiv_rn((float)w, 127.0f), 2.0f), 1.0f);
            float fs = (float)(1 << f);
            float a = __fmul_rn(__fmul_rn(__fmul_rn(__fsub_rn(g, ctr), stdv), HALF_PI), fs);
            scos[idx] = (float)cos((double)a);
        }
    }
    __syncthreads();

    float w[16];
    size_t base = (size_t)n * K_REAL + 1024 + (ax ? 4 : 0) + s;
#pragma unroll
    for (int f = 0; f < 16; f++) w[f] = w1[base + 8 * f];
    float* outp = (ax ? g_CY : g_CX) + ((size_t)(b * 4 + s) * 64) * HID + n;
#pragma unroll 2
    for (int j = 0; j < 64; j++) {
        float acc = 0.f;
#pragma unroll
        for (int f = 0; f < 16; f++) acc += w[f] * scos[f * 64 + j];
        outp[(size_t)j * HID] = acc;
    }
}

// ---------------------------------------------------------------------------
// Launch 3: U fold: U[b][s][n] = sum_c W1[n, 4c+s] * gestalt[b, c]
// ---------------------------------------------------------------------------
__global__ void u_kernel(const float* __restrict__ w1,
                         const float* __restrict__ gestalt) {
    int n = (blockIdx.x & 3) * 256 + threadIdx.x;
    int b = blockIdx.x >> 2;
    const float4* wrow = (const float4*)(w1 + (size_t)n * K_REAL);
    const float* g = gestalt + b * 256;
    float a0 = 0.f, a1 = 0.f, a2 = 0.f, a3 = 0.f;
#pragma unroll 4
    for (int c = 0; c < 256; c++) {
        float4 w = wrow[c];
        float gv = g[c];
        a0 += w.x * gv; a1 += w.y * gv; a2 += w.z * gv; a3 += w.w * gv;
    }
    g_U[(b * 4 + 0) * HID + n] = a0;
    g_U[(b * 4 + 1) * HID + n] = a1;
    g_U[(b * 4 + 2) * HID + n] = a2;
    g_U[(b * 4 + 3) * HID + n] = a3;
}

// ---------------------------------------------------------------------------
// Launch 4 (ncu slot): Fused H.
// h[t,n]=b1[n]+sum_s m_s*(U+CX[j]+CY[i]+d_s*Wd); SiLU; fp16 out.
// ---------------------------------------------------------------------------
#define FH_SMEM (16672 * 4)

__global__ __launch_bounds__(256) void fused_h_kernel(
    const float* __restrict__ mask, const float* __restrict__ depth,
    const float* __restrict__ w1, const float* __restrict__ b1) {
    extern __shared__ float sm[];
    float* sCX = sm;             // [s][j][nl]  4*64*32
    float* sCY = sm + 8192;      // [s][i][nl]
    float* sU  = sm + 16384;     // [s][nl]
    float* sWd = sm + 16512;     // [s][nl]
    float* sB  = sm + 16640;     // [nl]

    const int b  = blockIdx.y;
    const int n0 = blockIdx.x * 32;
    const int tid = threadIdx.x;

    for (int idx = tid; idx < 8192; idx += 256) {
        int nl = idx & 31, j = (idx >> 5) & 63, s = idx >> 11;
        size_t go = ((size_t)(b * 4 + s) * 64 + j) * HID + n0 + nl;
        sCX[idx] = g_CX[go];
        sCY[idx] = g_CY[go];
    }
    if (tid < 128) {
        int s = tid >> 5, nl = tid & 31;
        sU[tid]  = g_U[(b * 4 + s) * HID + n0 + nl];
        sWd[tid] = w1[(size_t)(n0 + nl) * K_REAL + 1152 + s];
    }
    if (tid < 32) sB[tid] = b1[n0 + tid];
    __syncthreads();

    const int npl = (tid & 7) * 4;    // 4 consecutive n
    const int tg  = tid >> 3;         // 32 i-groups

    float us[4][4], wds[4][4], bbs[4];
#pragma unroll
    for (int s = 0; s < 4; s++) {
        float4 tu = *(float4*)&sU[s * 32 + npl];
        us[s][0] = tu.x; us[s][1] = tu.y; us[s][2] = tu.z; us[s][3] = tu.w;
        float4 tw = *(float4*)&sWd[s * 32 + npl];
        wds[s][0] = tw.x; wds[s][1] = tw.y; wds[s][2] = tw.z; wds[s][3] = tw.w;
    }
    {
        float4 tb = *(float4*)&sB[npl];
        bbs[0] = tb.x; bbs[1] = tb.y; bbs[2] = tb.z; bbs[3] = tb.w;
    }

#pragma unroll 1
    for (int ib = 0; ib < 2; ib++) {
        int i = ib * 32 + tg;
        float uc[4][4];
#pragma unroll
        for (int s = 0; s < 4; s++) {
            float4 tc = *(float4*)&sCY[s * 2048 + i * 32 + npl];
            uc[s][0] = us[s][0] + tc.x;
            uc[s][1] = us[s][1] + tc.y;
            uc[s][2] = us[s][2] + tc.z;
            uc[s][3] = us[s][3] + tc.w;
        }
        const float* mrow = mask  + b * 16384 + i * 256;
        const float* drow = depth + b * 16384 + i * 256;
        size_t rowbase = ((size_t)(b * 4096 + i * 64)) * HID + n0 + npl;
#pragma unroll 2
        for (int j = 0; j < 64; j++) {
            float m00 = mrow[2 * j],       m01 = mrow[2 * j + 1];
            float m10 = mrow[2 * j + 128], m11 = mrow[2 * j + 129];
            float d00 = drow[2 * j],       d01 = drow[2 * j + 1];
            float d10 = drow[2 * j + 128], d11 = drow[2 * j + 129];
            float4 cx0 = *(float4*)&sCX[0 * 2048 + j * 32 + npl];
            float4 cx1 = *(float4*)&sCX[1 * 2048 + j * 32 + npl];
            float4 cx2 = *(float4*)&sCX[2 * 2048 + j * 32 + npl];
            float4 cx3 = *(float4*)&sCX[3 * 2048 + j * 32 + npl];
            float cxs[4][4];
            cxs[0][0] = cx0.x; cxs[0][1] = cx0.y; cxs[0][2] = cx0.z; cxs[0][3] = cx0.w;
            cxs[1][0] = cx1.x; cxs[1][1] = cx1.y; cxs[1][2] = cx1.z; cxs[1][3] = cx1.w;
            cxs[2][0] = cx2.x; cxs[2][1] = cx2.y; cxs[2][2] = cx2.z; cxs[2][3] = cx2.w;
            cxs[3][0] = cx3.x; cxs[3][1] = cx3.y; cxs[3][2] = cx3.z; cxs[3][3] = cx3.w;
            union { __half h4[4]; uint2 u2; } HP;
#pragma unroll
            for (int q = 0; q < 4; q++) {
                float h = bbs[q];
                h += m00 * (uc[0][q] + cxs[0][q] + d00 * wds[0][q]);
                h += m01 * (uc[1][q] + cxs[1][q] + d01 * wds[1][q]);
                h += m10 * (uc[2][q] + cxs[2][q] + d10 * wds[2][q]);
                h += m11 * (uc[3][q] + cxs[3][q] + d11 * wds[3][q]);
                float v = __fdividef(h, 1.0f + __expf(-h));
                HP.h4[q] = __float2half_rn(v);
            }
            __stcs((uint2*)(g_Hh + rowbase + (size_t)j * HID), HP.u2);
        }
    }
}

// ---------------------------------------------------------------------------
// Launch 5: single-pass fp16 GEMM via mma.sync: C = A * B^T.
// CTA 128x128, BK=32, 8 warps (4Mx2N). 4-stage cp.async, ONE sync per iter.
// ---------------------------------------------------------------------------
#define BM 128
#define BN 128
#define BK 32
#define ROWB 80
#define TILE_B (BM * ROWB)      // 10240
#define OFF_A 0
#define OFF_B TILE_B
#define STAGE_B (2 * TILE_B)    // 20480
#define NSTAGE 4
#define SMEM_DYN (NSTAGE * STAGE_B)  // 81920

__device__ __forceinline__ void cp_chunk(uint32_t st,
                                         const __half* A, const __half* B,
                                         int K, int k0, int tid) {
#pragma unroll
    for (int it = 0; it < 2; it++) {
        int idx = tid + it * 256;
        int r = idx >> 2, q = idx & 3;
        uint32_t o = (uint32_t)(r * ROWB + q * 16);
        size_t so = (size_t)r * K + k0 + q * 8;
        cp_async16(st + OFF_A + o, A + so);
        cp_async16(st + OFF_B + o, B + so);
    }
}

__global__ __launch_bounds__(256, 2) void gemm2_f16(
    const __half* __restrict__ A_g, const __half* __restrict__ B_g,
    int K, int NCH, const float* __restrict__ bias, float* __restrict__ outp) {
    extern __shared__ char dsm[];
    uint32_t sb = smem_u32(dsm);

    const int tid = threadIdx.x;
    const int wid = tid >> 5;
    const int L = tid & 31;
    const int m0 = blockIdx.y * BM;
    const int n0 = blockIdx.x * BN;
    const int warp_m = (wid >> 1) * 32;
    const int warp_n = (wid & 1) * 64;

    const __half* A = A_g + (size_t)m0 * K;
    const __half* B = B_g + (size_t)n0 * K;

    const int rowA = warp_m + (L & 7) + ((L >> 3) & 1) * 8;
    const int colA = (L >> 4) * 8;
    const int rowB = warp_n + (L & 7) + (L >> 4) * 8;
    const int colB = ((L >> 3) & 1) * 8;

    float d[2][8][4];
#pragma unroll
    for (int i = 0; i < 2; i++)
#pragma unroll
        for (int j = 0; j < 8; j++)
#pragma unroll
            for (int e = 0; e < 4; e++) d[i][j][e] = 0.0f;

    // prefetch stages 0..2
#pragma unroll
    for (int p = 0; p < NSTAGE - 1; p++) {
        cp_chunk(sb + p * STAGE_B, A, B, K, p * BK, tid);
        CP_COMMIT();
    }

    int stage = 0;
    for (int c = 0; c < NCH; c++) {
        // ensure chunk c complete (exact tail handling)
        int rem = NCH - 1 - c;
        if (rem >= 3) { CP_WAIT(2); }
        else if (rem == 2) { CP_WAIT(2); }
        else if (rem == 1) { CP_WAIT(1); }
        else { CP_WAIT(0); }
        __syncthreads();
        // issue the next stage AFTER the sync: slot stage+3 (mod 4) was fully
        // consumed at iter c-1 (all warps passed this barrier since), so the
        // overwrite is race-free with a single barrier per iteration.
        if (c + NSTAGE - 1 < NCH) {
            int ps = stage + NSTAGE - 1; if (ps >= NSTAGE) ps -= NSTAGE;
            cp_chunk(sb + ps * STAGE_B, A, B, K, (c + NSTAGE - 1) * BK, tid);
            CP_COMMIT();
        }

        uint32_t st = sb + stage * STAGE_B;
#pragma unroll
        for (int ks = 0; ks < 2; ks++) {
            uint32_t aoff = (uint32_t)((ks * 16 + colA) * 2);
            uint32_t boff = (uint32_t)((ks * 16 + colB) * 2);
            uint32_t ah[2][4], bh[4][4];
#pragma unroll
            for (int mt = 0; mt < 2; mt++)
                ldsm_x4(ah[mt], st + OFF_A + (uint32_t)((rowA + mt * 16) * ROWB) + aoff);
#pragma unroll
            for (int np = 0; np < 4; np++)
                ldsm_x4(bh[np], st + OFF_B + (uint32_t)((rowB + np * 16) * ROWB) + boff);
#pragma unroll
            for (int mt = 0; mt < 2; mt++)
#pragma unroll
                for (int np = 0; np < 4; np++) {
                    mma_f16(d[mt][np * 2],     ah[mt], bh[np][0], bh[np][1]);
                    mma_f16(d[mt][np * 2 + 1], ah[mt], bh[np][2], bh[np][3]);
                }
        }
        stage++; if (stage >= NSTAGE) stage = 0;
    }

#pragma unroll
    for (int mt = 0; mt < 2; mt++) {
#pragma unroll
        for (int np = 0; np < 4; np++) {
#pragma unroll
            for (int o = 0; o < 2; o++) {
                const float* dd = d[mt][np * 2 + o];
                int nb = n0 + warp_n + np * 16 + o * 8 + 2 * (L & 3);
                float bv0 = __ldg(bias + nb);
                float bv1 = __ldg(bias + nb + 1);
#pragma unroll
                for (int h = 0; h < 2; h++) {
                    int m = m0 + warp_m + mt * 16 + (L >> 2) + h * 8;
                    size_t obase = ((size_t)(m >> 12) << 20) + (size_t)(m & 4095);
                    __stcs(outp + obase + ((size_t)nb << 12), dd[2 * h] + bv0);
                    __stcs(outp + obase + ((size_t)(nb + 1) << 12), dd[2 * h + 1] + bv1);
                }
            }
        }
    }
}

// ---------------------------------------------------------------------------
extern "C" void kernel_launch(void* const* d_in, const int* in_sizes, int n_in,
                              void* d_out, int out_size) {
    const float* position = (const float*)d_in[0];
    const float* gestalt  = (const float*)d_in[1];
    const float* mask     = (const float*)d_in[2];
    const float* depth    = (const float*)d_in[3];
    const float* w1       = (const float*)d_in[4];
    const float* b1       = (const float*)d_in[5];
    const float* w2       = (const float*)d_in[6];
    const float* b2       = (const float*)d_in[7];
    float* out = (float*)d_out;
    (void)in_sizes; (void)n_in; (void)out_size;

    cudaFuncSetAttribute(gemm2_f16, cudaFuncAttributeMaxDynamicSharedMemorySize, SMEM_DYN);
    cudaFuncSetAttribute(fused_h_kernel, cudaFuncAttributeMaxDynamicSharedMemorySize, FH_SMEM);

    __half *w2h, *hh;
    cudaGetSymbolAddress((void**)&w2h, g_W2h);
    cudaGetSymbolAddress((void**)&hh, g_Hh);

    // Launch 1: W2 convert
    w2conv_kernel<<<(NOUT * HID + 255) / 256, 256>>>(w2);
    // Launch 2: CX/CY (inline cos)
    cxy_kernel<<<dim3(4, 4, 32), 256>>>(w1, position);
    // Launch 3: U fold
    u_kernel<<<64, 256>>>(w1, gestalt);
    // Launch 4 (ncu capture slot): fused H
    fused_h_kernel<<<dim3(32, 16), 256, FH_SMEM>>>(mask, depth, w1, b1);
    // Launch 5: gemm2
    dim3 grid2(NOUT / BN, T_TOK / BM);  // (2, 512)
    gemm2_f16<<<grid2, 256, SMEM_DYN>>>(hh, w2h, HID, HID / BK, b2, out);
}

// round 10
// speedup vs baseline: 15.5167x; 1.2741x over previous
#include <cuda_runtime.h>
#include <cuda_fp16.h>
#include <math.h>
#include <stdint.h>

#define T_TOK 65536      // B * (H/2) * (W/2)
#define K_REAL 1156
#define HID 1024
#define NOUT 256

// ---------------- scratch (device globals; allocation-free) ----------------
__device__ __align__(16) __half g_Hh[(size_t)T_TOK * HID];
__device__ __align__(16) __half g_W2h[NOUT * HID];
__device__ __align__(16) float g_U[16 * 4 * HID];        // [b][s][n]
__device__ __align__(16) float g_CX[16 * 4 * 64 * HID];  // [b][s][j][n]
__device__ __align__(16) float g_CY[16 * 4 * 64 * HID];  // [b][s][i][n]

// ---------------- PTX helpers (baseline PTX only) ----------------
__device__ __forceinline__ uint32_t smem_u32(const void* p) {
    uint32_t a;
    asm("{ .reg .u64 t; cvta.to.shared.u64 t, %1; cvt.u32.u64 %0, t; }"
        : "=r"(a) : "l"(p));
    return a;
}
__device__ __forceinline__ void cp_async16(uint32_t dst, const void* src) {
    asm volatile("cp.async.cg.shared.global [%0], [%1], 16;"
                 :: "r"(dst), "l"(src));
}
#define CP_COMMIT() asm volatile("cp.async.commit_group;" ::: "memory")
#define CP_WAIT(n)  asm volatile("cp.async.wait_group %0;" :: "n"(n) : "memory")

__device__ __forceinline__ void ldsm_x4(uint32_t* r, uint32_t addr) {
    asm volatile("ldmatrix.sync.aligned.m8n8.x4.shared.b16 {%0,%1,%2,%3}, [%4];"
                 : "=r"(r[0]), "=r"(r[1]), "=r"(r[2]), "=r"(r[3]) : "r"(addr));
}
__device__ __forceinline__ void mma_f16(float* d, const uint32_t* a,
                                        uint32_t b0, uint32_t b1) {
    asm volatile("mma.sync.aligned.m16n8k16.row.col.f32.f16.f16.f32 "
                 "{%0,%1,%2,%3}, {%4,%5,%6,%7}, {%8,%9}, {%0,%1,%2,%3};"
                 : "+f"(d[0]), "+f"(d[1]), "+f"(d[2]), "+f"(d[3])
                 : "r"(a[0]), "r"(a[1]), "r"(a[2]), "r"(a[3]), "r"(b0), "r"(b1));
}
// pack two fp32 -> fp16x2 (lo = first arg)
__device__ __forceinline__ uint32_t pack_f16x2(float lo, float hi) {
    uint32_t r;
    asm("cvt.rn.f16x2.f32 %0, %1, %2;" : "=r"(r) : "f"(hi), "f"(lo));
    return r;
}

// ---------------------------------------------------------------------------
// Launch 1: W2 fp16 convert
// ---------------------------------------------------------------------------
__global__ void w2conv_kernel(const float* __restrict__ w2) {
    int idx = blockIdx.x * 256 + threadIdx.x;
    if (idx < NOUT * HID) g_W2h[idx] = __float2half_rn(w2[idx]);
}

// ---------------------------------------------------------------------------
// Launch 2: CX/CY with inline cos table (bit-exact fp32 arg chain + double cos)
// ---------------------------------------------------------------------------
__global__ void cxy_kernel(const float* __restrict__ w1,
                           const float* __restrict__ pos) {
    __shared__ float scos[1024];   // [f][j] for this (ax, b, sub)
    int n = blockIdx.x * 256 + threadIdx.x;
    int s = blockIdx.y;
    int bz = blockIdx.z;
    int b = bz & 15;
    int ax = bz >> 4;
    int sub = ax ? (s >> 1) : (s & 1);

    {
        const float HALF_PI = 1.57079632679489661923f;
        float pw = pos[b * 4 + 3];
        float stdv = __fdiv_rn(0.1f, fminf(fmaxf(pw, 0.0078125f), 0.5f));
        float ctr = fminf(fmaxf(pos[b * 4 + (ax ? 1 : 0)], -1.f), 1.f);
#pragma unroll
        for (int k = 0; k < 4; k++) {
            int idx = threadIdx.x + k * 256;
            int f = idx >> 6;
            int j = idx & 63;
            int w = 2 * j + sub;
            float g = __fsub_rn(__fmul_rn(__fdiv_rn((float)w, 127.0f), 2.0f), 1.0f);
            float fs = (float)(1 << f);
            float a = __fmul_rn(__fmul_rn(__fmul_rn(__fsub_rn(g, ctr), stdv), HALF_PI), fs);
            scos[idx] = (float)cos((double)a);
        }
    }
    __syncthreads();

    float w[16];
    size_t base = (size_t)n * K_REAL + 1024 + (ax ? 4 : 0) + s;
#pragma unroll
    for (int f = 0; f < 16; f++) w[f] = w1[base + 8 * f];
    float* outp = (ax ? g_CY : g_CX) + ((size_t)(b * 4 + s) * 64) * HID + n;
#pragma unroll 2
    for (int j = 0; j < 64; j++) {
        float acc = 0.f;
#pragma unroll
        for (int f = 0; f < 16; f++) acc += w[f] * scos[f * 64 + j];
        outp[(size_t)j * HID] = acc;
    }
}

// ---------------------------------------------------------------------------
// Launch 3: U fold: U[b][s][n] = sum_c W1[n, 4c+s] * gestalt[b, c]
// ---------------------------------------------------------------------------
__global__ void u_kernel(const float* __restrict__ w1,
                         const float* __restrict__ gestalt) {
    int n = (blockIdx.x & 3) * 256 + threadIdx.x;
    int b = blockIdx.x >> 2;
    const float4* wrow = (const float4*)(w1 + (size_t)n * K_REAL);
    const float* g = gestalt + b * 256;
    float a0 = 0.f, a1 = 0.f, a2 = 0.f, a3 = 0.f;
#pragma unroll 4
    for (int c = 0; c < 256; c++) {
        float4 w = wrow[c];
        float gv = g[c];
        a0 += w.x * gv; a1 += w.y * gv; a2 += w.z * gv; a3 += w.w * gv;
    }
    g_U[(b * 4 + 0) * HID + n] = a0;
    g_U[(b * 4 + 1) * HID + n] = a1;
    g_U[(b * 4 + 2) * HID + n] = a2;
    g_U[(b * 4 + 3) * HID + n] = a3;
}

// ---------------------------------------------------------------------------
// Launch 4 (ncu slot): Fused H, i-split 4-way for wave balance.
// h[t,n]=b1[n]+sum_s m_s*(U+CX[j]+CY[i]+d_s*Wd); SiLU; fp16 out.
// grid (32 ngroups, 16 b, 4 isplit), 256 threads, 3 CTAs/SM.
// Thread map: npl=(tid&7)*4 (4 n), il=(tid>>3)&15 (i), jh=tid>>7 (j half).
// smem: sCX [4][64][32]=32KB, sCY [4][16][32]=8KB, +U/Wd/B.
// ---------------------------------------------------------------------------
#define FH_SMEM (10528 * 4)

__global__ __launch_bounds__(256, 3) void fused_h_kernel(
    const float* __restrict__ mask, const float* __restrict__ depth,
    const float* __restrict__ w1, const float* __restrict__ b1) {
    extern __shared__ float sm[];
    float* sCX = sm;              // [s][j(64)][nl(32)]
    float* sCY = sm + 8192;       // [s][il(16)][nl(32)]
    float* sU  = sm + 10240;      // [s][nl]
    float* sWd = sm + 10368;      // [s][nl]
    float* sB  = sm + 10496;      // [nl]

    const int b  = blockIdx.y;
    const int n0 = blockIdx.x * 32;
    const int iz = blockIdx.z;
    const int tid = threadIdx.x;

    for (int idx = tid; idx < 8192; idx += 256) {
        int nl = idx & 31, j = (idx >> 5) & 63, s = idx >> 11;
        sCX[idx] = g_CX[((size_t)(b * 4 + s) * 64 + j) * HID + n0 + nl];
    }
    for (int idx = tid; idx < 2048; idx += 256) {
        int nl = idx & 31, il = (idx >> 5) & 15, s = idx >> 9;
        sCY[idx] = g_CY[((size_t)(b * 4 + s) * 64 + iz * 16 + il) * HID + n0 + nl];
    }
    if (tid < 128) {
        int s = tid >> 5, nl = tid & 31;
        sU[tid]  = g_U[(b * 4 + s) * HID + n0 + nl];
        sWd[tid] = w1[(size_t)(n0 + nl) * K_REAL + 1152 + s];
    }
    if (tid < 32) sB[tid] = b1[n0 + tid];
    __syncthreads();

    const int npl = (tid & 7) * 4;     // 4 consecutive n
    const int tg  = tid >> 3;          // 0..31
    const int il  = tg & 15;           // i within split
    const int jh  = tg >> 4;           // j half (0/1)
    const int i   = iz * 16 + il;

    float uc[4][4], wds[4][4], bbs[4];
#pragma unroll
    for (int s = 0; s < 4; s++) {
        float4 tu = *(float4*)&sU[s * 32 + npl];
        float4 tc = *(float4*)&sCY[s * 512 + il * 32 + npl];
        uc[s][0] = tu.x + tc.x; uc[s][1] = tu.y + tc.y;
        uc[s][2] = tu.z + tc.z; uc[s][3] = tu.w + tc.w;
        float4 tw = *(float4*)&sWd[s * 32 + npl];
        wds[s][0] = tw.x; wds[s][1] = tw.y; wds[s][2] = tw.z; wds[s][3] = tw.w;
    }
    {
        float4 tb = *(float4*)&sB[npl];
        bbs[0] = tb.x; bbs[1] = tb.y; bbs[2] = tb.z; bbs[3] = tb.w;
    }

    const float* mrow = mask  + b * 16384 + i * 256 + jh * 64;
    const float* drow = depth + b * 16384 + i * 256 + jh * 64;
    const float* cxb  = sCX + (jh * 32) * 32 + npl;   // j-local offset within sCX rows
    size_t rowbase = ((size_t)(b * 4096 + i * 64 + jh * 32)) * HID + n0 + npl;

#pragma unroll 2
    for (int jp = 0; jp < 16; jp++) {      // 2 j per iteration
        float4 mv0 = *(const float4*)&mrow[jp * 4];          // row 2i,   pixels 4jp..+3
        float4 mv1 = *(const float4*)&mrow[jp * 4 + 128];    // row 2i+1
        float4 dv0 = *(const float4*)&drow[jp * 4];
        float4 dv1 = *(const float4*)&drow[jp * 4 + 128];
#pragma unroll
        for (int t = 0; t < 2; t++) {
            float m00 = t ? mv0.z : mv0.x;
            float m01 = t ? mv0.w : mv0.y;
            float m10 = t ? mv1.z : mv1.x;
            float m11 = t ? mv1.w : mv1.y;
            float d00 = t ? dv0.z : dv0.x;
            float d01 = t ? dv0.w : dv0.y;
            float d10 = t ? dv1.z : dv1.x;
            float d11 = t ? dv1.w : dv1.y;
            int jl = jp * 2 + t;
            float4 cx0 = *(float4*)&cxb[0 * 2048 + jl * 32];
            float4 cx1 = *(float4*)&cxb[1 * 2048 + jl * 32];
            float4 cx2 = *(float4*)&cxb[2 * 2048 + jl * 32];
            float4 cx3 = *(float4*)&cxb[3 * 2048 + jl * 32];
            float cxs[4][4];
            cxs[0][0] = cx0.x; cxs[0][1] = cx0.y; cxs[0][2] = cx0.z; cxs[0][3] = cx0.w;
            cxs[1][0] = cx1.x; cxs[1][1] = cx1.y; cxs[1][2] = cx1.z; cxs[1][3] = cx1.w;
            cxs[2][0] = cx2.x; cxs[2][1] = cx2.y; cxs[2][2] = cx2.z; cxs[2][3] = cx2.w;
            cxs[3][0] = cx3.x; cxs[3][1] = cx3.y; cxs[3][2] = cx3.z; cxs[3][3] = cx3.w;
            float v[4];
#pragma unroll
            for (int q = 0; q < 4; q++) {
                float h = bbs[q];
                h += m00 * (uc[0][q] + cxs[0][q] + d00 * wds[0][q]);
                h += m01 * (uc[1][q] + cxs[1][q] + d01 * wds[1][q]);
                h += m10 * (uc[2][q] + cxs[2][q] + d10 * wds[2][q]);
                h += m11 * (uc[3][q] + cxs[3][q] + d11 * wds[3][q]);
                v[q] = __fdividef(h, 1.0f + __expf(-h));
            }
            uint2 o;
            o.x = pack_f16x2(v[0], v[1]);
            o.y = pack_f16x2(v[2], v[3]);
            __stcs((uint2*)(g_Hh + rowbase + (size_t)jl * HID), o);
        }
    }
}

// ---------------------------------------------------------------------------
// Launch 5: single-pass fp16 GEMM via mma.sync: C = A * B^T (verified R9).
// CTA 128x128, BK=32, 8 warps (4Mx2N). 4-stage cp.async, one sync per iter.
// ---------------------------------------------------------------------------
#define BM 128
#define BN 128
#define BK 32
#define ROWB 80
#define TILE_B (BM * ROWB)      // 10240
#define OFF_A 0
#define OFF_B TILE_B
#define STAGE_B (2 * TILE_B)    // 20480
#define NSTAGE 4
#define SMEM_DYN (NSTAGE * STAGE_B)  // 81920

__device__ __forceinline__ void cp_chunk(uint32_t st,
                                         const __half* A, const __half* B,
                                         int K, int k0, int tid) {
#pragma unroll
    for (int it = 0; it < 2; it++) {
        int idx = tid + it * 256;
        int r = idx >> 2, q = idx & 3;
        uint32_t o = (uint32_t)(r * ROWB + q * 16);
        size_t so = (size_t)r * K + k0 + q * 8;
        cp_async16(st + OFF_A + o, A + so);
        cp_async16(st + OFF_B + o, B + so);
    }
}

__global__ __launch_bounds__(256, 2) void gemm2_f16(
    const __half* __restrict__ A_g, const __half* __restrict__ B_g,
    int K, int NCH, const float* __restrict__ bias, float* __restrict__ outp) {
    extern __shared__ char dsm[];
    uint32_t sb = smem_u32(dsm);

    const int tid = threadIdx.x;
    const int wid = tid >> 5;
    const int L = tid & 31;
    const int m0 = blockIdx.y * BM;
    const int n0 = blockIdx.x * BN;
    const int warp_m = (wid >> 1) * 32;
    const int warp_n = (wid & 1) * 64;

    const __half* A = A_g + (size_t)m0 * K;
    const __half* B = B_g + (size_t)n0 * K;

    const int rowA = warp_m + (L & 7) + ((L >> 3) & 1) * 8;
    const int colA = (L >> 4) * 8;
    const int rowB = warp_n + (L & 7) + (L >> 4) * 8;
    const int colB = ((L >> 3) & 1) * 8;

    float d[2][8][4];
#pragma unroll
    for (int i = 0; i < 2; i++)
#pragma unroll
        for (int j = 0; j < 8; j++)
#pragma unroll
            for (int e = 0; e < 4; e++) d[i][j][e] = 0.0f;

#pragma unroll
    for (int p = 0; p < NSTAGE - 1; p++) {
        cp_chunk(sb + p * STAGE_B, A, B, K, p * BK, tid);
        CP_COMMIT();
    }

    int stage = 0;
    for (int c = 0; c < NCH; c++) {
        int rem = NCH - 1 - c;
        if (rem >= 2) { CP_WAIT(2); }
        else if (rem == 1) { CP_WAIT(1); }
        else { CP_WAIT(0); }
        __syncthreads();
        if (c + NSTAGE - 1 < NCH) {
            int ps = stage + NSTAGE - 1; if (ps >= NSTAGE) ps -= NSTAGE;
            cp_chunk(sb + ps * STAGE_B, A, B, K, (c + NSTAGE - 1) * BK, tid);
            CP_COMMIT();
        }

        uint32_t st = sb + stage * STAGE_B;
#pragma unroll
        for (int ks = 0; ks < 2; ks++) {
            uint32_t aoff = (uint32_t)((ks * 16 + colA) * 2);
            uint32_t boff = (uint32_t)((ks * 16 + colB) * 2);
            uint32_t ah[2][4], bh[4][4];
#pragma unroll
            for (int mt = 0; mt < 2; mt++)
                ldsm_x4(ah[mt], st + OFF_A + (uint32_t)((rowA + mt * 16) * ROWB) + aoff);
#pragma unroll
            for (int np = 0; np < 4; np++)
                ldsm_x4(bh[np], st + OFF_B + (uint32_t)((rowB + np * 16) * ROWB) + boff);
#pragma unroll
            for (int mt = 0; mt < 2; mt++)
#pragma unroll
                for (int np = 0; np < 4; np++) {
                    mma_f16(d[mt][np * 2],     ah[mt], bh[np][0], bh[np][1]);
                    mma_f16(d[mt][np * 2 + 1], ah[mt], bh[np][2], bh[np][3]);
                }
        }
        stage++; if (stage >= NSTAGE) stage = 0;
    }

#pragma unroll
    for (int mt = 0; mt < 2; mt++) {
#pragma unroll
        for (int np = 0; np < 4; np++) {
#pragma unroll
            for (int o = 0; o < 2; o++) {
                const float* dd = d[mt][np * 2 + o];
                int nb = n0 + warp_n + np * 16 + o * 8 + 2 * (L & 3);
                float bv0 = __ldg(bias + nb);
                float bv1 = __ldg(bias + nb + 1);
#pragma unroll
                for (int h = 0; h < 2; h++) {
                    int m = m0 + warp_m + mt * 16 + (L >> 2) + h * 8;
                    size_t obase = ((size_t)(m >> 12) << 20) + (size_t)(m & 4095);
                    __stcs(outp + obase + ((size_t)nb << 12), dd[2 * h] + bv0);
                    __stcs(outp + obase + ((size_t)(nb + 1) << 12), dd[2 * h + 1] + bv1);
                }
            }
        }
    }
}

// ---------------------------------------------------------------------------
extern "C" void kernel_launch(void* const* d_in, const int* in_sizes, int n_in,
                              void* d_out, int out_size) {
    const float* position = (const float*)d_in[0];
    const float* gestalt  = (const float*)d_in[1];
    const float* mask     = (const float*)d_in[2];
    const float* depth    = (const float*)d_in[3];
    const float* w1       = (const float*)d_in[4];
    const float* b1       = (const float*)d_in[5];
    const float* w2       = (const float*)d_in[6];
    const float* b2       = (const float*)d_in[7];
    float* out = (float*)d_out;
    (void)in_sizes; (void)n_in; (void)out_size;

    cudaFuncSetAttribute(gemm2_f16, cudaFuncAttributeMaxDynamicSharedMemorySize, SMEM_DYN);
    cudaFuncSetAttribute(fused_h_kernel, cudaFuncAttributeMaxDynamicSharedMemorySize, FH_SMEM);

    __half *w2h, *hh;
    cudaGetSymbolAddress((void**)&w2h, g_W2h);
    cudaGetSymbolAddress((void**)&hh, g_Hh);

    // Launch 1: W2 convert
    w2conv_kernel<<<(NOUT * HID + 255) / 256, 256>>>(w2);
    // Launch 2: CX/CY (inline cos)
    cxy_kernel<<<dim3(4, 4, 32), 256>>>(w1, position);
    // Launch 3: U fold
    u_kernel<<<64, 256>>>(w1, gestalt);
    // Launch 4 (ncu capture slot): fused H (i-split 4-way)
    fused_h_kernel<<<dim3(32, 16, 4), 256, FH_SMEM>>>(mask, depth, w1, b1);
    // Launch 5: gemm2
    dim3 grid2(NOUT / BN, T_TOK / BM);  // (2, 512)
    gemm2_f16<<<grid2, 256, SMEM_DYN>>>(hh, w2h, HID, HID / BK, b2, out);
}